// round 1
// baseline (speedup 1.0000x reference)
#include <cuda_runtime.h>
#include <math.h>

// Problem constants (B=2, T=2048, C=1024, H=16, D=64)
#define B_  2
#define T_  2048
#define C_  1024
#define H_  16
#define D_  64
#define M_  (B_*T_)        // 4096 rows for the projections

// Scratch: q, k, v, attention output y  (each B*T*C floats = 16 MB)
__device__ float g_q[B_*T_*C_];
__device__ float g_k[B_*T_*C_];
__device__ float g_v[B_*T_*C_];
__device__ float g_y[B_*T_*C_];

// ----------------------------------------------------------------------------
// Tiled fp32 GEMM: C[M,N] = A[M,K] @ B[K,N]
// 128x128 block, K-tile 16, 256 threads, 8x8 per thread.
// ----------------------------------------------------------------------------
__global__ __launch_bounds__(256) void gemm_kernel(
    const float* __restrict__ A, const float* __restrict__ Bw,
    float* __restrict__ Co, int Mdim, int N, int K)
{
    __shared__ float As[16][128];   // transposed: As[k][m]
    __shared__ float Bs[16][128];   // Bs[k][n]

    const int tid = threadIdx.x;
    const int bm = blockIdx.y * 128;
    const int bn = blockIdx.x * 128;
    const int ty = tid >> 4;        // 0..15
    const int tx = tid & 15;        // 0..15

    float acc[8][8];
    #pragma unroll
    for (int i = 0; i < 8; i++)
        #pragma unroll
        for (int j = 0; j < 8; j++)
            acc[i][j] = 0.0f;

    // A-load mapping: 128 rows x 16 k = 512 float4 -> 2 per thread
    const int a_row = tid >> 1;            // 0..127
    const int a_kg  = (tid & 1) * 8;       // 0 or 8

    for (int k0 = 0; k0 < K; k0 += 16) {
        // Load A tile (transposed into As)
        #pragma unroll
        for (int it = 0; it < 2; it++) {
            const int kg = a_kg + it * 4;
            float4 v4 = *(const float4*)(A + (size_t)(bm + a_row) * K + k0 + kg);
            As[kg + 0][a_row] = v4.x;
            As[kg + 1][a_row] = v4.y;
            As[kg + 2][a_row] = v4.z;
            As[kg + 3][a_row] = v4.w;
        }
        // Load B tile: 16 rows x 128 cols = 512 float4 -> 2 per thread
        #pragma unroll
        for (int it = 0; it < 2; it++) {
            const int idx = it * 256 + tid;
            const int brow = idx >> 5;          // 0..15
            const int bcg  = (idx & 31) * 4;    // 0..124
            float4 v4 = *(const float4*)(Bw + (size_t)(k0 + brow) * N + bn + bcg);
            *(float4*)&Bs[brow][bcg] = v4;
        }
        __syncthreads();

        #pragma unroll
        for (int kk = 0; kk < 16; kk++) {
            float a[8], b[8];
            *(float4*)&a[0] = *(const float4*)&As[kk][ty * 8];
            *(float4*)&a[4] = *(const float4*)&As[kk][ty * 8 + 4];
            *(float4*)&b[0] = *(const float4*)&Bs[kk][tx * 8];
            *(float4*)&b[4] = *(const float4*)&Bs[kk][tx * 8 + 4];
            #pragma unroll
            for (int i = 0; i < 8; i++)
                #pragma unroll
                for (int j = 0; j < 8; j++)
                    acc[i][j] += a[i] * b[j];
        }
        __syncthreads();
    }

    // Epilogue
    #pragma unroll
    for (int i = 0; i < 8; i++) {
        const size_t row = (size_t)(bm + ty * 8 + i);
        float4 r0 = make_float4(acc[i][0], acc[i][1], acc[i][2], acc[i][3]);
        float4 r1 = make_float4(acc[i][4], acc[i][5], acc[i][6], acc[i][7]);
        *(float4*)(Co + row * N + bn + tx * 8)     = r0;
        *(float4*)(Co + row * N + bn + tx * 8 + 4) = r1;
    }
}

// ----------------------------------------------------------------------------
// Fused RoPE + RMSNorm over q and k. One warp per (b,t,h) row of D=64.
// Pairs (i, i+32): y1 = x1*c - x2*s ; y2 = x1*s + x2*c ; then rmsnorm.
// ----------------------------------------------------------------------------
__global__ __launch_bounds__(256) void rope_rms_kernel(
    float* __restrict__ q, float* __restrict__ k,
    const float* __restrict__ cosb, const float* __restrict__ sinb)
{
    const int warp = threadIdx.x >> 5;
    const int lane = threadIdx.x & 31;
    const size_t row = (size_t)blockIdx.x * 8 + warp;   // (b*T + t)*H + h
    const int t = (int)((row / H_) % T_);

    const float c = cosb[t * D_ + lane];
    const float s = sinb[t * D_ + lane];

    #pragma unroll
    for (int w = 0; w < 2; w++) {
        float* p = (w ? k : q) + row * D_;
        const float x1 = p[lane];
        const float x2 = p[lane + 32];
        const float y1 = x1 * c - x2 * s;
        const float y2 = x1 * s + x2 * c;
        float ss = y1 * y1 + y2 * y2;
        #pragma unroll
        for (int m = 16; m > 0; m >>= 1)
            ss += __shfl_xor_sync(0xffffffffu, ss, m);
        const float r = rsqrtf(ss * (1.0f / 64.0f) + 1e-6f);
        p[lane]      = y1 * r;
        p[lane + 32] = y2 * r;
    }
}

// ----------------------------------------------------------------------------
// Flash attention, fp32, causal. 64x64 tiles, D=64.
// Grid: (T/64, H, B). 256 threads as 16x16, each computes 4x4.
// Shared: Qt (Q transposed [d][m]), KP (K transposed [d][n], reused for P[m][n]),
//         Vs ([n][d]). 3 * 16KB = exactly 48KB static.
// ----------------------------------------------------------------------------
__global__ __launch_bounds__(256) void flash_kernel(
    const float* __restrict__ Q, const float* __restrict__ Kmat,
    const float* __restrict__ V, float* __restrict__ O)
{
    __shared__ float Qt[64][64];
    __shared__ float KP[64][64];
    __shared__ float Vs[64][64];

    const int tid = threadIdx.x;
    const int ty = tid >> 4;          // 0..15
    const int tx = tid & 15;          // 0..15
    const int b = blockIdx.z, h = blockIdx.y;
    const int q0 = blockIdx.x * 64;

    const int lr = tid >> 2;          // 0..63  (row during loads)
    const int dg = (tid & 3) * 16;    // d base during loads

    const size_t rowstride = (size_t)H_ * D_;  // 1024

    // Load Q tile transposed
    const float* qb = Q + ((size_t)(b * T_ + q0) * H_ + h) * D_;
    #pragma unroll
    for (int i = 0; i < 4; i++) {
        float4 v4 = *(const float4*)(qb + (size_t)lr * rowstride + dg + 4 * i);
        Qt[dg + 4*i + 0][lr] = v4.x;
        Qt[dg + 4*i + 1][lr] = v4.y;
        Qt[dg + 4*i + 2][lr] = v4.z;
        Qt[dg + 4*i + 3][lr] = v4.w;
    }

    float m_i[4], l_i[4], o_acc[4][4];
    #pragma unroll
    for (int i = 0; i < 4; i++) {
        m_i[i] = -1e30f; l_i[i] = 0.0f;
        #pragma unroll
        for (int j = 0; j < 4; j++) o_acc[i][j] = 0.0f;
    }

    const int ntile = blockIdx.x + 1;   // causal: only tiles j <= qtile
    for (int jt = 0; jt < ntile; jt++) {
        const int k0 = jt * 64;
        __syncthreads();   // prior P reads + Qt visibility / Vs reuse

        // Load K (transposed) and V tiles
        const float* kb = Kmat + ((size_t)(b * T_ + k0) * H_ + h) * D_;
        const float* vb = V    + ((size_t)(b * T_ + k0) * H_ + h) * D_;
        #pragma unroll
        for (int i = 0; i < 4; i++) {
            float4 kv4 = *(const float4*)(kb + (size_t)lr * rowstride + dg + 4 * i);
            KP[dg + 4*i + 0][lr] = kv4.x;
            KP[dg + 4*i + 1][lr] = kv4.y;
            KP[dg + 4*i + 2][lr] = kv4.z;
            KP[dg + 4*i + 3][lr] = kv4.w;
            float4 vv4 = *(const float4*)(vb + (size_t)lr * rowstride + dg + 4 * i);
            *(float4*)&Vs[lr][dg + 4*i] = vv4;
        }
        __syncthreads();

        // S = Q K^T (4x4 per thread)
        float s[4][4];
        #pragma unroll
        for (int i = 0; i < 4; i++)
            #pragma unroll
            for (int j = 0; j < 4; j++) s[i][j] = 0.0f;

        #pragma unroll 16
        for (int d = 0; d < 64; d++) {
            float4 qv = *(const float4*)&Qt[d][ty * 4];
            float4 kv = *(const float4*)&KP[d][tx * 4];
            s[0][0] += qv.x * kv.x; s[0][1] += qv.x * kv.y; s[0][2] += qv.x * kv.z; s[0][3] += qv.x * kv.w;
            s[1][0] += qv.y * kv.x; s[1][1] += qv.y * kv.y; s[1][2] += qv.y * kv.z; s[1][3] += qv.y * kv.w;
            s[2][0] += qv.z * kv.x; s[2][1] += qv.z * kv.y; s[2][2] += qv.z * kv.z; s[2][3] += qv.z * kv.w;
            s[3][0] += qv.w * kv.x; s[3][1] += qv.w * kv.y; s[3][2] += qv.w * kv.z; s[3][3] += qv.w * kv.w;
        }

        // scale + causal mask
        #pragma unroll
        for (int i = 0; i < 4; i++)
            #pragma unroll
            for (int j = 0; j < 4; j++) {
                s[i][j] *= 0.125f;   // 1/sqrt(64)
                if (q0 + ty * 4 + i < k0 + tx * 4 + j) s[i][j] = -1e30f;
            }

        // Online softmax
        #pragma unroll
        for (int i = 0; i < 4; i++) {
            float mt = fmaxf(fmaxf(s[i][0], s[i][1]), fmaxf(s[i][2], s[i][3]));
            mt = fmaxf(mt, __shfl_xor_sync(0xffffffffu, mt, 1));
            mt = fmaxf(mt, __shfl_xor_sync(0xffffffffu, mt, 2));
            mt = fmaxf(mt, __shfl_xor_sync(0xffffffffu, mt, 4));
            mt = fmaxf(mt, __shfl_xor_sync(0xffffffffu, mt, 8));
            const float mn = fmaxf(m_i[i], mt);
            const float alpha = __expf(m_i[i] - mn);
            float rs = 0.0f;
            #pragma unroll
            for (int j = 0; j < 4; j++) {
                s[i][j] = __expf(s[i][j] - mn);
                rs += s[i][j];
            }
            rs += __shfl_xor_sync(0xffffffffu, rs, 1);
            rs += __shfl_xor_sync(0xffffffffu, rs, 2);
            rs += __shfl_xor_sync(0xffffffffu, rs, 4);
            rs += __shfl_xor_sync(0xffffffffu, rs, 8);
            l_i[i] = l_i[i] * alpha + rs;
            m_i[i] = mn;
            #pragma unroll
            for (int j = 0; j < 4; j++) o_acc[i][j] *= alpha;
        }

        __syncthreads();   // all K reads done -> safe to overwrite KP with P
        #pragma unroll
        for (int i = 0; i < 4; i++)
            *(float4*)&KP[ty * 4 + i][tx * 4] =
                make_float4(s[i][0], s[i][1], s[i][2], s[i][3]);
        __syncthreads();

        // O += P @ V
        #pragma unroll
        for (int j0 = 0; j0 < 64; j0 += 4) {
            float4 vv0 = *(const float4*)&Vs[j0 + 0][tx * 4];
            float4 vv1 = *(const float4*)&Vs[j0 + 1][tx * 4];
            float4 vv2 = *(const float4*)&Vs[j0 + 2][tx * 4];
            float4 vv3 = *(const float4*)&Vs[j0 + 3][tx * 4];
            #pragma unroll
            for (int i = 0; i < 4; i++) {
                float4 pp = *(const float4*)&KP[ty * 4 + i][j0];
                o_acc[i][0] += pp.x * vv0.x + pp.y * vv1.x + pp.z * vv2.x + pp.w * vv3.x;
                o_acc[i][1] += pp.x * vv0.y + pp.y * vv1.y + pp.z * vv2.y + pp.w * vv3.y;
                o_acc[i][2] += pp.x * vv0.z + pp.y * vv1.z + pp.z * vv2.z + pp.w * vv3.z;
                o_acc[i][3] += pp.x * vv0.w + pp.y * vv1.w + pp.z * vv2.w + pp.w * vv3.w;
            }
        }
    }

    // Normalize and write out
    float* ob = O + ((size_t)(b * T_ + q0) * H_ + h) * D_;
    #pragma unroll
    for (int i = 0; i < 4; i++) {
        const float inv = 1.0f / l_i[i];
        float4 r = make_float4(o_acc[i][0] * inv, o_acc[i][1] * inv,
                               o_acc[i][2] * inv, o_acc[i][3] * inv);
        *(float4*)(ob + (size_t)(ty * 4 + i) * rowstride + tx * 4) = r;
    }
}

// ----------------------------------------------------------------------------
// Launch
// ----------------------------------------------------------------------------
extern "C" void kernel_launch(void* const* d_in, const int* in_sizes, int n_in,
                              void* d_out, int out_size)
{
    const float* x    = (const float*)d_in[0];
    const float* cosb = (const float*)d_in[1];
    const float* sinb = (const float*)d_in[2];
    const float* Wq   = (const float*)d_in[3];
    const float* Wk   = (const float*)d_in[4];
    const float* Wv   = (const float*)d_in[5];
    const float* Wp   = (const float*)d_in[6];
    float* out = (float*)d_out;

    float *q, *k, *v, *y;
    cudaGetSymbolAddress((void**)&q, g_q);
    cudaGetSymbolAddress((void**)&k, g_k);
    cudaGetSymbolAddress((void**)&v, g_v);
    cudaGetSymbolAddress((void**)&y, g_y);

    dim3 ggrid(C_ / 128, M_ / 128);   // (8, 32)
    gemm_kernel<<<ggrid, 256>>>(x, Wq, q, M_, C_, C_);
    gemm_kernel<<<ggrid, 256>>>(x, Wk, k, M_, C_, C_);
    gemm_kernel<<<ggrid, 256>>>(x, Wv, v, M_, C_, C_);

    rope_rms_kernel<<<(B_ * T_ * H_) / 8, 256>>>(q, k, cosb, sinb);

    dim3 fgrid(T_ / 64, H_, B_);      // (32, 16, 2)
    flash_kernel<<<fgrid, 256>>>(q, k, v, y);

    gemm_kernel<<<ggrid, 256>>>(y, Wp, out, M_, C_, C_);
}

// round 2
// speedup vs baseline: 2.2253x; 2.2253x over previous
#include <cuda_runtime.h>
#include <math.h>
#include <stdint.h>

// Problem constants (B=2, T=2048, C=1024, H=16, D=64)
#define B_  2
#define T_  2048
#define C_  1024
#define H_  16
#define D_  64
#define M_  (B_*T_)        // 4096 rows for the projections

// Scratch: q, k, v, attention output y  (each B*T*C floats = 16 MB)
__device__ float g_q[B_*T_*C_];
__device__ float g_k[B_*T_*C_];
__device__ float g_v[B_*T_*C_];
__device__ float g_y[B_*T_*C_];

// ----------------------------------------------------------------------------
// Helpers: tf32 convert + m16n8k8 tf32 mma
// ----------------------------------------------------------------------------
__device__ __forceinline__ uint32_t f2tf(float x) {
    uint32_t y;
    asm("cvt.rna.tf32.f32 %0, %1;" : "=r"(y) : "f"(x));
    return y;
}

__device__ __forceinline__ void mma_tf32(float* c, const uint32_t* a,
                                         uint32_t b0, uint32_t b1) {
    asm volatile(
        "mma.sync.aligned.m16n8k8.row.col.f32.tf32.tf32.f32 "
        "{%0,%1,%2,%3}, {%4,%5,%6,%7}, {%8,%9}, {%0,%1,%2,%3};"
        : "+f"(c[0]), "+f"(c[1]), "+f"(c[2]), "+f"(c[3])
        : "r"(a[0]), "r"(a[1]), "r"(a[2]), "r"(a[3]), "r"(b0), "r"(b1));
}

// ----------------------------------------------------------------------------
// TF32 GEMM: C[M,N] = A[M,K] @ B[K,N].  128x128 tile, BK=32, 256 threads.
// 8 warps -> warp tile 32(M) x 64(N) = 2 mtiles x 8 ntiles of m16n8.
// ----------------------------------------------------------------------------
#define GBM 128
#define GBN 128
#define GBK 32
#define GPAD 8

__global__ __launch_bounds__(256) void gemm_tf32(
    const float* __restrict__ A, const float* __restrict__ Bw,
    float* __restrict__ Co, int N, int K)
{
    __shared__ uint32_t As[GBK][GBM + GPAD];   // [k][m]
    __shared__ uint32_t Bs[GBK][GBN + GPAD];   // [k][n]

    const int tid  = threadIdx.x;
    const int lane = tid & 31;
    const int wid  = tid >> 5;
    const int wm   = wid >> 1;       // 0..3
    const int wn   = wid & 1;        // 0..1
    const int bm = blockIdx.y * GBM;
    const int bn = blockIdx.x * GBN;
    const int r = lane >> 2;         // 0..7
    const int cq = lane & 3;         // 0..3

    float acc[2][8][4];
    #pragma unroll
    for (int mt = 0; mt < 2; mt++)
        #pragma unroll
        for (int nt = 0; nt < 8; nt++)
            #pragma unroll
            for (int i = 0; i < 4; i++) acc[mt][nt][i] = 0.0f;

    const int a_row = tid >> 1;            // 0..127
    const int a_kb  = (tid & 1) * 16;      // 0 or 16

    for (int k0 = 0; k0 < K; k0 += GBK) {
        // A tile: 128 x 32 floats -> transposed into As[k][m]
        #pragma unroll
        for (int it = 0; it < 4; it++) {
            const int kk = a_kb + it * 4;
            float4 v4 = *(const float4*)(A + (size_t)(bm + a_row) * K + k0 + kk);
            As[kk + 0][a_row] = f2tf(v4.x);
            As[kk + 1][a_row] = f2tf(v4.y);
            As[kk + 2][a_row] = f2tf(v4.z);
            As[kk + 3][a_row] = f2tf(v4.w);
        }
        // B tile: 32 x 128 floats
        #pragma unroll
        for (int it = 0; it < 4; it++) {
            const int idx  = it * 256 + tid;
            const int brow = idx >> 5;          // 0..31
            const int bcg  = (idx & 31) * 4;
            float4 v4 = *(const float4*)(Bw + (size_t)(k0 + brow) * N + bn + bcg);
            uint4 u = make_uint4(f2tf(v4.x), f2tf(v4.y), f2tf(v4.z), f2tf(v4.w));
            *(uint4*)&Bs[brow][bcg] = u;
        }
        __syncthreads();

        #pragma unroll
        for (int kk = 0; kk < 4; kk++) {
            const int kb = kk * 8;
            uint32_t af[2][4];
            #pragma unroll
            for (int mt = 0; mt < 2; mt++) {
                const int row = wm * 32 + mt * 16 + r;
                af[mt][0] = As[kb + cq][row];
                af[mt][1] = As[kb + cq][row + 8];
                af[mt][2] = As[kb + cq + 4][row];
                af[mt][3] = As[kb + cq + 4][row + 8];
            }
            #pragma unroll
            for (int nt = 0; nt < 8; nt++) {
                const int col = wn * 64 + nt * 8 + r;
                const uint32_t b0 = Bs[kb + cq][col];
                const uint32_t b1 = Bs[kb + cq + 4][col];
                mma_tf32(acc[0][nt], af[0], b0, b1);
                mma_tf32(acc[1][nt], af[1], b0, b1);
            }
        }
        __syncthreads();
    }

    // Epilogue: c0,c1 -> (row, 2c), c2,c3 -> (row+8, 2c)
    #pragma unroll
    for (int mt = 0; mt < 2; mt++) {
        const int row = bm + wm * 32 + mt * 16 + r;
        #pragma unroll
        for (int nt = 0; nt < 8; nt++) {
            const int col = bn + wn * 64 + nt * 8 + cq * 2;
            *(float2*)(Co + (size_t)row * N + col) =
                make_float2(acc[mt][nt][0], acc[mt][nt][1]);
            *(float2*)(Co + (size_t)(row + 8) * N + col) =
                make_float2(acc[mt][nt][2], acc[mt][nt][3]);
        }
    }
}

// ----------------------------------------------------------------------------
// Fused RoPE + RMSNorm over q and k. One warp per (b,t,h) row of D=64.
// ----------------------------------------------------------------------------
__global__ __launch_bounds__(256) void rope_rms_kernel(
    float* __restrict__ q, float* __restrict__ k,
    const float* __restrict__ cosb, const float* __restrict__ sinb)
{
    const int warp = threadIdx.x >> 5;
    const int lane = threadIdx.x & 31;
    const size_t row = (size_t)blockIdx.x * 8 + warp;   // (b*T + t)*H + h
    const int t = (int)((row / H_) % T_);

    const float c = cosb[t * D_ + lane];
    const float s = sinb[t * D_ + lane];

    #pragma unroll
    for (int w = 0; w < 2; w++) {
        float* p = (w ? k : q) + row * D_;
        const float x1 = p[lane];
        const float x2 = p[lane + 32];
        const float y1 = x1 * c - x2 * s;
        const float y2 = x1 * s + x2 * c;
        float ss = y1 * y1 + y2 * y2;
        #pragma unroll
        for (int m = 16; m > 0; m >>= 1)
            ss += __shfl_xor_sync(0xffffffffu, ss, m);
        const float r = rsqrtf(ss * (1.0f / 64.0f) + 1e-6f);
        p[lane]      = y1 * r;
        p[lane + 32] = y2 * r;
    }
}

// ----------------------------------------------------------------------------
// Flash attention, tf32 mma, causal. 64x64 tiles, D=64, 128 threads (4 warps).
// Warp w owns q rows [w*16, w*16+16). Q frags persistent in registers.
// Ks: K transposed [d][kpos] (stride 72, conflict-free B-frags);
//     reused as P [qrow][kpos] between S and PV.
// Vs: [kpos][d] (stride 72, conflict-free B-frags).
// ----------------------------------------------------------------------------
#define FSTR 72

__global__ __launch_bounds__(128) void flash_tf32(
    const float* __restrict__ Q, const float* __restrict__ Kmat,
    const float* __restrict__ V, float* __restrict__ O)
{
    __shared__ uint32_t Ks[64][FSTR];
    __shared__ uint32_t Vs[64][FSTR];

    const int tid  = threadIdx.x;
    const int lane = tid & 31;
    const int warp = tid >> 5;         // 0..3
    const int r  = lane >> 2;          // 0..7
    const int cq = lane & 3;           // 0..3
    const int b = blockIdx.z, h = blockIdx.y;
    const int q0 = blockIdx.x * 64;
    const int m0 = warp * 16;

    const size_t rowstride = (size_t)H_ * D_;  // 1024

    // ---- Stage Q through Ks, pull A-fragments into registers ----
    const float* qb = Q + ((size_t)(b * T_ + q0) * H_ + h) * D_;
    #pragma unroll
    for (int it = 0; it < 8; it++) {
        const int idx = it * 128 + tid;
        const int row = idx >> 4;            // 0..63
        const int dg  = (idx & 15) * 4;
        float4 v4 = *(const float4*)(qb + (size_t)row * rowstride + dg);
        uint4 u = make_uint4(f2tf(v4.x), f2tf(v4.y), f2tf(v4.z), f2tf(v4.w));
        *(uint4*)&Ks[row][dg] = u;
    }
    __syncthreads();

    uint32_t qa[8][4];
    #pragma unroll
    for (int kk = 0; kk < 8; kk++) {
        const int kb = kk * 8;
        qa[kk][0] = Ks[m0 + r][kb + cq];
        qa[kk][1] = Ks[m0 + r + 8][kb + cq];
        qa[kk][2] = Ks[m0 + r][kb + cq + 4];
        qa[kk][3] = Ks[m0 + r + 8][kb + cq + 4];
    }

    float m_lo = -1e30f, m_hi = -1e30f, l_lo = 0.0f, l_hi = 0.0f;
    float oacc[8][4];
    #pragma unroll
    for (int dt = 0; dt < 8; dt++)
        #pragma unroll
        for (int i = 0; i < 4; i++) oacc[dt][i] = 0.0f;

    const int ntile = blockIdx.x + 1;
    for (int jt = 0; jt < ntile; jt++) {
        const int k0 = jt * 64;
        __syncthreads();   // protect Ks (Q-stage / P) + Vs from prior iter

        // Load K (transposed into Ks[d][kpos]) and V (Vs[kpos][d])
        const float* kb = Kmat + ((size_t)(b * T_ + k0) * H_ + h) * D_;
        const float* vb = V    + ((size_t)(b * T_ + k0) * H_ + h) * D_;
        #pragma unroll
        for (int it = 0; it < 8; it++) {
            const int idx  = it * 128 + tid;
            const int kpos = idx >> 4;
            const int dg   = (idx & 15) * 4;
            float4 kv4 = *(const float4*)(kb + (size_t)kpos * rowstride + dg);
            Ks[dg + 0][kpos] = f2tf(kv4.x);
            Ks[dg + 1][kpos] = f2tf(kv4.y);
            Ks[dg + 2][kpos] = f2tf(kv4.z);
            Ks[dg + 3][kpos] = f2tf(kv4.w);
            float4 vv4 = *(const float4*)(vb + (size_t)kpos * rowstride + dg);
            uint4 u = make_uint4(f2tf(vv4.x), f2tf(vv4.y), f2tf(vv4.z), f2tf(vv4.w));
            *(uint4*)&Vs[kpos][dg] = u;
        }
        __syncthreads();

        // ---- S = Q @ K^T ----
        float sacc[8][4];
        #pragma unroll
        for (int nt = 0; nt < 8; nt++)
            #pragma unroll
            for (int i = 0; i < 4; i++) sacc[nt][i] = 0.0f;

        #pragma unroll
        for (int kk = 0; kk < 8; kk++) {
            const int kb2 = kk * 8;
            #pragma unroll
            for (int nt = 0; nt < 8; nt++) {
                const int col = nt * 8 + r;
                const uint32_t b0 = Ks[kb2 + cq][col];
                const uint32_t b1 = Ks[kb2 + cq + 4][col];
                mma_tf32(sacc[nt], qa[kk], b0, b1);
            }
        }

        // ---- scale + causal mask ----
        const int row_lo = q0 + m0 + r;
        const int row_hi = row_lo + 8;
        #pragma unroll
        for (int nt = 0; nt < 8; nt++) {
            const int c0 = k0 + nt * 8 + cq * 2;
            sacc[nt][0] = (row_lo >= c0    ) ? sacc[nt][0] * 0.125f : -1e30f;
            sacc[nt][1] = (row_lo >= c0 + 1) ? sacc[nt][1] * 0.125f : -1e30f;
            sacc[nt][2] = (row_hi >= c0    ) ? sacc[nt][2] * 0.125f : -1e30f;
            sacc[nt][3] = (row_hi >= c0 + 1) ? sacc[nt][3] * 0.125f : -1e30f;
        }

        // ---- online softmax (rows distributed over lane&3 groups) ----
        float mt_lo = -1e30f, mt_hi = -1e30f;
        #pragma unroll
        for (int nt = 0; nt < 8; nt++) {
            mt_lo = fmaxf(mt_lo, fmaxf(sacc[nt][0], sacc[nt][1]));
            mt_hi = fmaxf(mt_hi, fmaxf(sacc[nt][2], sacc[nt][3]));
        }
        mt_lo = fmaxf(mt_lo, __shfl_xor_sync(0xffffffffu, mt_lo, 1));
        mt_lo = fmaxf(mt_lo, __shfl_xor_sync(0xffffffffu, mt_lo, 2));
        mt_hi = fmaxf(mt_hi, __shfl_xor_sync(0xffffffffu, mt_hi, 1));
        mt_hi = fmaxf(mt_hi, __shfl_xor_sync(0xffffffffu, mt_hi, 2));

        const float mn_lo = fmaxf(m_lo, mt_lo);
        const float mn_hi = fmaxf(m_hi, mt_hi);
        const float al_lo = __expf(m_lo - mn_lo);
        const float al_hi = __expf(m_hi - mn_hi);

        float rs_lo = 0.0f, rs_hi = 0.0f;
        #pragma unroll
        for (int nt = 0; nt < 8; nt++) {
            sacc[nt][0] = __expf(sacc[nt][0] - mn_lo);
            sacc[nt][1] = __expf(sacc[nt][1] - mn_lo);
            sacc[nt][2] = __expf(sacc[nt][2] - mn_hi);
            sacc[nt][3] = __expf(sacc[nt][3] - mn_hi);
            rs_lo += sacc[nt][0] + sacc[nt][1];
            rs_hi += sacc[nt][2] + sacc[nt][3];
        }
        rs_lo += __shfl_xor_sync(0xffffffffu, rs_lo, 1);
        rs_lo += __shfl_xor_sync(0xffffffffu, rs_lo, 2);
        rs_hi += __shfl_xor_sync(0xffffffffu, rs_hi, 1);
        rs_hi += __shfl_xor_sync(0xffffffffu, rs_hi, 2);

        l_lo = l_lo * al_lo + rs_lo;
        l_hi = l_hi * al_hi + rs_hi;
        m_lo = mn_lo; m_hi = mn_hi;
        #pragma unroll
        for (int dt = 0; dt < 8; dt++) {
            oacc[dt][0] *= al_lo; oacc[dt][1] *= al_lo;
            oacc[dt][2] *= al_hi; oacc[dt][3] *= al_hi;
        }

        // ---- write P into Ks as [qrow][kpos] ----
        __syncthreads();   // all Ks (K) reads done
        #pragma unroll
        for (int nt = 0; nt < 8; nt++) {
            const int cc = nt * 8 + cq * 2;
            *(uint2*)&Ks[m0 + r][cc]     = make_uint2(f2tf(sacc[nt][0]), f2tf(sacc[nt][1]));
            *(uint2*)&Ks[m0 + r + 8][cc] = make_uint2(f2tf(sacc[nt][2]), f2tf(sacc[nt][3]));
        }
        __syncthreads();

        // ---- O += P @ V ----
        #pragma unroll
        for (int kk = 0; kk < 8; kk++) {
            const int kb2 = kk * 8;
            uint32_t pa[4];
            pa[0] = Ks[m0 + r][kb2 + cq];
            pa[1] = Ks[m0 + r + 8][kb2 + cq];
            pa[2] = Ks[m0 + r][kb2 + cq + 4];
            pa[3] = Ks[m0 + r + 8][kb2 + cq + 4];
            #pragma unroll
            for (int dt = 0; dt < 8; dt++) {
                const int col = dt * 8 + r;
                const uint32_t b0 = Vs[kb2 + cq][col];
                const uint32_t b1 = Vs[kb2 + cq + 4][col];
                mma_tf32(oacc[dt], pa, b0, b1);
            }
        }
    }

    // ---- normalize + store ----
    const float inv_lo = 1.0f / l_lo;
    const float inv_hi = 1.0f / l_hi;
    float* ob = O + ((size_t)(b * T_ + q0) * H_ + h) * D_;
    #pragma unroll
    for (int dt = 0; dt < 8; dt++) {
        const int cc = dt * 8 + cq * 2;
        *(float2*)(ob + (size_t)(m0 + r) * rowstride + cc) =
            make_float2(oacc[dt][0] * inv_lo, oacc[dt][1] * inv_lo);
        *(float2*)(ob + (size_t)(m0 + r + 8) * rowstride + cc) =
            make_float2(oacc[dt][2] * inv_hi, oacc[dt][3] * inv_hi);
    }
}

// ----------------------------------------------------------------------------
// Launch
// ----------------------------------------------------------------------------
extern "C" void kernel_launch(void* const* d_in, const int* in_sizes, int n_in,
                              void* d_out, int out_size)
{
    const float* x    = (const float*)d_in[0];
    const float* cosb = (const float*)d_in[1];
    const float* sinb = (const float*)d_in[2];
    const float* Wq   = (const float*)d_in[3];
    const float* Wk   = (const float*)d_in[4];
    const float* Wv   = (const float*)d_in[5];
    const float* Wp   = (const float*)d_in[6];
    float* out = (float*)d_out;

    float *q, *k, *v, *y;
    cudaGetSymbolAddress((void**)&q, g_q);
    cudaGetSymbolAddress((void**)&k, g_k);
    cudaGetSymbolAddress((void**)&v, g_v);
    cudaGetSymbolAddress((void**)&y, g_y);

    dim3 ggrid(C_ / GBN, M_ / GBM);   // (8, 32)
    gemm_tf32<<<ggrid, 256>>>(x, Wq, q, C_, C_);
    gemm_tf32<<<ggrid, 256>>>(x, Wk, k, C_, C_);
    gemm_tf32<<<ggrid, 256>>>(x, Wv, v, C_, C_);

    rope_rms_kernel<<<(B_ * T_ * H_) / 8, 256>>>(q, k, cosb, sinb);

    dim3 fgrid(T_ / 64, H_, B_);      // (32, 16, 2)
    flash_tf32<<<fgrid, 128>>>(q, k, v, y);

    gemm_tf32<<<ggrid, 256>>>(y, Wp, out, C_, C_);
}

// round 4
// speedup vs baseline: 2.9897x; 1.3435x over previous
#include <cuda_runtime.h>
#include <math.h>
#include <stdint.h>

// Problem constants (B=2, T=2048, C=1024, H=16, D=64)
#define B_  2
#define T_  2048
#define C_  1024
#define H_  16
#define D_  64
#define M_  (B_*T_)        // 4096 rows for the projections

// Scratch: q, k, v, attention output y  (each B*T*C floats = 16 MB)
__device__ float g_q[B_*T_*C_];
__device__ float g_k[B_*T_*C_];
__device__ float g_v[B_*T_*C_];
__device__ float g_y[B_*T_*C_];

// ----------------------------------------------------------------------------
// Helpers
// ----------------------------------------------------------------------------
__device__ __forceinline__ uint32_t f2tf(float x) {
    uint32_t y;
    asm("cvt.rna.tf32.f32 %0, %1;" : "=r"(y) : "f"(x));
    return y;
}

__device__ __forceinline__ void mma_tf32(float* c, const uint32_t* a,
                                         uint32_t b0, uint32_t b1) {
    asm volatile(
        "mma.sync.aligned.m16n8k8.row.col.f32.tf32.tf32.f32 "
        "{%0,%1,%2,%3}, {%4,%5,%6,%7}, {%8,%9}, {%0,%1,%2,%3};"
        : "+f"(c[0]), "+f"(c[1]), "+f"(c[2]), "+f"(c[3])
        : "r"(a[0]), "r"(a[1]), "r"(a[2]), "r"(a[3]), "r"(b0), "r"(b1));
}

__device__ __forceinline__ void cpasync16(void* s, const void* g) {
    uint32_t sp = (uint32_t)__cvta_generic_to_shared(s);
    asm volatile("cp.async.cg.shared.global [%0], [%1], 16;" :: "r"(sp), "l"(g));
}
#define CP_COMMIT() asm volatile("cp.async.commit_group;" ::: "memory")
template <int N> __device__ __forceinline__ void cp_wait() {
    asm volatile("cp.async.wait_group %0;" :: "n"(N) : "memory");
}

// ----------------------------------------------------------------------------
// TF32 GEMM: C[M,N] = A[M,K] @ B[K,N], M=4096, N=K=1024.
// 128x128 tile, BK=32, 256 threads, cp.async double-buffered.
// A smem [m][k] stride 36 (36%32=4 -> frag addr 4r+cq conflict-free).
// B smem [k][n] stride 136 (136%32=8 -> frag addr conflict-free).
// ----------------------------------------------------------------------------
#define GBM 128
#define GBN 128
#define GBK 32
#define ASTR 36
#define BSTR 136
#define NKT (C_/GBK)
#define GEMM_SMEM ((2*GBM*ASTR + 2*GBK*BSTR) * 4)   // 71680 B

__global__ __launch_bounds__(256, 2) void gemm_tf32(
    const float* __restrict__ A, const float* __restrict__ Bw,
    float* __restrict__ Co)
{
    extern __shared__ float sm[];
    float* Ab0 = sm;
    float* Ab1 = sm + GBM * ASTR;
    float* Bb0 = sm + 2 * GBM * ASTR;
    float* Bb1 = Bb0 + GBK * BSTR;

    const int tid  = threadIdx.x;
    const int lane = tid & 31;
    const int wid  = tid >> 5;
    const int wm   = wid >> 1;       // 0..3
    const int wn   = wid & 1;        // 0..1
    const int bm = blockIdx.y * GBM;
    const int bn = blockIdx.x * GBN;
    const int r  = lane >> 2;        // 0..7
    const int cq = lane & 3;         // 0..3

    float acc[2][8][4];
    #pragma unroll
    for (int mt = 0; mt < 2; mt++)
        #pragma unroll
        for (int nt = 0; nt < 8; nt++)
            #pragma unroll
            for (int i = 0; i < 4; i++) acc[mt][nt][i] = 0.0f;

    #define GEMM_PREFETCH(kt, Abuf, Bbuf)                                     \
    {                                                                         \
        const float* Ag = A + (size_t)bm * C_ + (kt) * GBK;                   \
        _Pragma("unroll")                                                     \
        for (int it = 0; it < 4; it++) {                                      \
            const int idx = it * 256 + tid;                                   \
            const int row = idx >> 3, ch = (idx & 7) * 4;                     \
            cpasync16((Abuf) + row * ASTR + ch, Ag + (size_t)row * C_ + ch);  \
        }                                                                     \
        const float* Bg = Bw + (size_t)((kt) * GBK) * C_ + bn;                \
        _Pragma("unroll")                                                     \
        for (int it = 0; it < 4; it++) {                                      \
            const int idx = it * 256 + tid;                                   \
            const int row = idx >> 5, ch = (idx & 31) * 4;                    \
            cpasync16((Bbuf) + row * BSTR + ch, Bg + (size_t)row * C_ + ch);  \
        }                                                                     \
    }

    GEMM_PREFETCH(0, Ab0, Bb0);
    CP_COMMIT();

    for (int kt = 0; kt < NKT; kt++) {
        if (kt + 1 < NKT) {
            if ((kt + 1) & 1) { GEMM_PREFETCH(kt + 1, Ab1, Bb1); }
            else              { GEMM_PREFETCH(kt + 1, Ab0, Bb0); }
            CP_COMMIT();
            cp_wait<1>();
        } else {
            cp_wait<0>();
        }
        __syncthreads();

        const float* As = (kt & 1) ? Ab1 : Ab0;
        const float* Bs = (kt & 1) ? Bb1 : Bb0;

        #pragma unroll
        for (int kk = 0; kk < 4; kk++) {
            const int kb = kk * 8;
            uint32_t af[2][4];
            #pragma unroll
            for (int mt = 0; mt < 2; mt++) {
                const int row = wm * 32 + mt * 16 + r;
                af[mt][0] = f2tf(As[(size_t)row * ASTR + kb + cq]);
                af[mt][1] = f2tf(As[(size_t)(row + 8) * ASTR + kb + cq]);
                af[mt][2] = f2tf(As[(size_t)row * ASTR + kb + cq + 4]);
                af[mt][3] = f2tf(As[(size_t)(row + 8) * ASTR + kb + cq + 4]);
            }
            #pragma unroll
            for (int nt = 0; nt < 8; nt++) {
                const int col = wn * 64 + nt * 8 + r;
                const uint32_t b0 = f2tf(Bs[(size_t)(kb + cq) * BSTR + col]);
                const uint32_t b1 = f2tf(Bs[(size_t)(kb + cq + 4) * BSTR + col]);
                mma_tf32(acc[0][nt], af[0], b0, b1);
                mma_tf32(acc[1][nt], af[1], b0, b1);
            }
        }
        __syncthreads();
    }

    // Epilogue
    #pragma unroll
    for (int mt = 0; mt < 2; mt++) {
        const int row = bm + wm * 32 + mt * 16 + r;
        #pragma unroll
        for (int nt = 0; nt < 8; nt++) {
            const int col = bn + wn * 64 + nt * 8 + cq * 2;
            *(float2*)(Co + (size_t)row * C_ + col) =
                make_float2(acc[mt][nt][0], acc[mt][nt][1]);
            *(float2*)(Co + (size_t)(row + 8) * C_ + col) =
                make_float2(acc[mt][nt][2], acc[mt][nt][3]);
        }
    }
}

// ----------------------------------------------------------------------------
// Fused RoPE + RMSNorm over q and k. One warp per (b,t,h) row of D=64.
// ----------------------------------------------------------------------------
__global__ __launch_bounds__(256) void rope_rms_kernel(
    float* __restrict__ q, float* __restrict__ k,
    const float* __restrict__ cosb, const float* __restrict__ sinb)
{
    const int warp = threadIdx.x >> 5;
    const int lane = threadIdx.x & 31;
    const size_t row = (size_t)blockIdx.x * 8 + warp;   // (b*T + t)*H + h
    const int t = (int)((row / H_) % T_);

    const float c = cosb[t * D_ + lane];
    const float s = sinb[t * D_ + lane];

    #pragma unroll
    for (int w = 0; w < 2; w++) {
        float* p = (w ? k : q) + row * D_;
        const float x1 = p[lane];
        const float x2 = p[lane + 32];
        const float y1 = x1 * c - x2 * s;
        const float y2 = x1 * s + x2 * c;
        float ss = y1 * y1 + y2 * y2;
        #pragma unroll
        for (int m = 16; m > 0; m >>= 1)
            ss += __shfl_xor_sync(0xffffffffu, ss, m);
        const float r = rsqrtf(ss * (1.0f / 64.0f) + 1e-6f);
        p[lane]      = y1 * r;
        p[lane + 32] = y2 * r;
    }
}

// ----------------------------------------------------------------------------
// Flash attention, tf32 mma, causal. 128-row q-tile, 64-row k-tiles, D=64.
// 256 threads (8 warps); warp w owns q rows [w*16, w*16+16).
// K/V cp.async double-buffered as [kpos][d]:
//   Ks stride 68, Vs stride 72 (conflict-free per fragment pattern).
// P buffer [qrow][kpos] stride 68, warp-private rows; also stages Q at start.
// ----------------------------------------------------------------------------
#define KSTR 68
#define VSTR 72
#define PSTR 68
#define FLASH_SMEM ((2*64*KSTR + 2*64*VSTR + 128*PSTR) * 4)   // 106496 B

__global__ __launch_bounds__(256) void flash_tf32(
    const float* __restrict__ Q, const float* __restrict__ Kmat,
    const float* __restrict__ V, float* __restrict__ O)
{
    extern __shared__ float fsm[];
    float* Kb0 = fsm;
    float* Kb1 = Kb0 + 64 * KSTR;
    float* Vb0 = Kb1 + 64 * KSTR;
    float* Vb1 = Vb0 + 64 * VSTR;
    float* Pb  = Vb1 + 64 * VSTR;
    uint32_t* Pbu = (uint32_t*)Pb;

    const int tid  = threadIdx.x;
    const int lane = tid & 31;
    const int warp = tid >> 5;         // 0..7
    const int r  = lane >> 2;          // 0..7
    const int cq = lane & 3;           // 0..3
    const int b = blockIdx.z, h = blockIdx.y;
    const int qi = (int)(gridDim.x - 1 - blockIdx.x);   // heavy blocks first
    const int q0 = qi * 128;
    const int m0 = warp * 16;

    const size_t rowstride = (size_t)H_ * D_;  // 1024

    const float* kbase = Kmat + ((size_t)(b * T_) * H_ + h) * D_;
    const float* vbase = V    + ((size_t)(b * T_) * H_ + h) * D_;

    // FIX (round 3 bug): full 64x64 tile coverage = 1024 x 16B chunks per
    // tensor -> 4 chunks per thread per tensor.
    #define KV_PREFETCH(jt, Kbuf, Vbuf)                                        \
    {                                                                          \
        _Pragma("unroll")                                                      \
        for (int it = 0; it < 4; it++) {                                       \
            const int idx  = it * 256 + tid;                                   \
            const int row  = idx >> 4;            /* 0..63 */                  \
            const int ch   = (idx & 15) * 4;      /* 0..60 */                  \
            const float* kg = kbase + (size_t)((jt) * 64 + row) * rowstride;   \
            const float* vg = vbase + (size_t)((jt) * 64 + row) * rowstride;   \
            cpasync16((Kbuf) + row * KSTR + ch, kg + ch);                      \
            cpasync16((Vbuf) + row * VSTR + ch, vg + ch);                      \
        }                                                                      \
    }

    // ---- Stage Q (raw fp32) into Pb; prefetch K/V tile 0 ----
    const float* qb = Q + ((size_t)(b * T_ + q0) * H_ + h) * D_;
    #pragma unroll
    for (int it = 0; it < 8; it++) {
        const int idx = it * 256 + tid;
        const int row = idx >> 4;
        const int ch  = (idx & 15) * 4;
        *(float4*)&Pb[row * PSTR + ch] =
            *(const float4*)(qb + (size_t)row * rowstride + ch);
    }
    KV_PREFETCH(0, Kb0, Vb0);
    CP_COMMIT();
    __syncthreads();

    // Pull Q A-fragments (tf32) into registers
    uint32_t qa[8][4];
    #pragma unroll
    for (int kk = 0; kk < 8; kk++) {
        const int kb = kk * 8;
        qa[kk][0] = f2tf(Pb[(m0 + r) * PSTR + kb + cq]);
        qa[kk][1] = f2tf(Pb[(m0 + r + 8) * PSTR + kb + cq]);
        qa[kk][2] = f2tf(Pb[(m0 + r) * PSTR + kb + cq + 4]);
        qa[kk][3] = f2tf(Pb[(m0 + r + 8) * PSTR + kb + cq + 4]);
    }

    float m_lo = -1e30f, m_hi = -1e30f, l_lo = 0.0f, l_hi = 0.0f;
    float oacc[8][4];
    #pragma unroll
    for (int dt = 0; dt < 8; dt++)
        #pragma unroll
        for (int i = 0; i < 4; i++) oacc[dt][i] = 0.0f;

    const int ntile = 2 * qi + 2;
    for (int jt = 0; jt < ntile; jt++) {
        __syncthreads();   // prior reads of the prefetch-target stage are done
        if (jt + 1 < ntile) {
            if ((jt + 1) & 1) { KV_PREFETCH(jt + 1, Kb1, Vb1); }
            else              { KV_PREFETCH(jt + 1, Kb0, Vb0); }
            CP_COMMIT();
            cp_wait<1>();
        } else {
            cp_wait<0>();
        }
        __syncthreads();

        const float* Ks = (jt & 1) ? Kb1 : Kb0;
        const float* Vs = (jt & 1) ? Vb1 : Vb0;
        const int k0 = jt * 64;

        // ---- S = Q @ K^T ----
        float sacc[8][4];
        #pragma unroll
        for (int nt = 0; nt < 8; nt++)
            #pragma unroll
            for (int i = 0; i < 4; i++) sacc[nt][i] = 0.0f;

        #pragma unroll
        for (int kk = 0; kk < 8; kk++) {
            const int kb2 = kk * 8;
            #pragma unroll
            for (int nt = 0; nt < 8; nt++) {
                const int col = nt * 8 + r;
                const uint32_t b0 = f2tf(Ks[col * KSTR + kb2 + cq]);
                const uint32_t b1 = f2tf(Ks[col * KSTR + kb2 + cq + 4]);
                mma_tf32(sacc[nt], qa[kk], b0, b1);
            }
        }

        // ---- scale (+ causal mask only on diagonal tiles) ----
        const int row_lo = q0 + m0 + r;
        const int row_hi = row_lo + 8;
        if (jt >= 2 * qi) {
            #pragma unroll
            for (int nt = 0; nt < 8; nt++) {
                const int c0 = k0 + nt * 8 + cq * 2;
                sacc[nt][0] = (row_lo >= c0    ) ? sacc[nt][0] * 0.125f : -1e30f;
                sacc[nt][1] = (row_lo >= c0 + 1) ? sacc[nt][1] * 0.125f : -1e30f;
                sacc[nt][2] = (row_hi >= c0    ) ? sacc[nt][2] * 0.125f : -1e30f;
                sacc[nt][3] = (row_hi >= c0 + 1) ? sacc[nt][3] * 0.125f : -1e30f;
            }
        } else {
            #pragma unroll
            for (int nt = 0; nt < 8; nt++) {
                sacc[nt][0] *= 0.125f; sacc[nt][1] *= 0.125f;
                sacc[nt][2] *= 0.125f; sacc[nt][3] *= 0.125f;
            }
        }

        // ---- online softmax (per-warp; rows r / r+8 of the warp's 16) ----
        float mt_lo = -1e30f, mt_hi = -1e30f;
        #pragma unroll
        for (int nt = 0; nt < 8; nt++) {
            mt_lo = fmaxf(mt_lo, fmaxf(sacc[nt][0], sacc[nt][1]));
            mt_hi = fmaxf(mt_hi, fmaxf(sacc[nt][2], sacc[nt][3]));
        }
        mt_lo = fmaxf(mt_lo, __shfl_xor_sync(0xffffffffu, mt_lo, 1));
        mt_lo = fmaxf(mt_lo, __shfl_xor_sync(0xffffffffu, mt_lo, 2));
        mt_hi = fmaxf(mt_hi, __shfl_xor_sync(0xffffffffu, mt_hi, 1));
        mt_hi = fmaxf(mt_hi, __shfl_xor_sync(0xffffffffu, mt_hi, 2));

        const float mn_lo = fmaxf(m_lo, mt_lo);
        const float mn_hi = fmaxf(m_hi, mt_hi);
        const float al_lo = __expf(m_lo - mn_lo);
        const float al_hi = __expf(m_hi - mn_hi);

        float rs_lo = 0.0f, rs_hi = 0.0f;
        #pragma unroll
        for (int nt = 0; nt < 8; nt++) {
            sacc[nt][0] = __expf(sacc[nt][0] - mn_lo);
            sacc[nt][1] = __expf(sacc[nt][1] - mn_lo);
            sacc[nt][2] = __expf(sacc[nt][2] - mn_hi);
            sacc[nt][3] = __expf(sacc[nt][3] - mn_hi);
            rs_lo += sacc[nt][0] + sacc[nt][1];
            rs_hi += sacc[nt][2] + sacc[nt][3];
        }
        rs_lo += __shfl_xor_sync(0xffffffffu, rs_lo, 1);
        rs_lo += __shfl_xor_sync(0xffffffffu, rs_lo, 2);
        rs_hi += __shfl_xor_sync(0xffffffffu, rs_hi, 1);
        rs_hi += __shfl_xor_sync(0xffffffffu, rs_hi, 2);

        l_lo = l_lo * al_lo + rs_lo;
        l_hi = l_hi * al_hi + rs_hi;
        m_lo = mn_lo; m_hi = mn_hi;
        #pragma unroll
        for (int dt = 0; dt < 8; dt++) {
            oacc[dt][0] *= al_lo; oacc[dt][1] *= al_lo;
            oacc[dt][2] *= al_hi; oacc[dt][3] *= al_hi;
        }

        // ---- write P (tf32 bits) to warp-private rows of Pb ----
        #pragma unroll
        for (int nt = 0; nt < 8; nt++) {
            const int cc = nt * 8 + cq * 2;
            *(uint2*)&Pbu[(m0 + r) * PSTR + cc] =
                make_uint2(f2tf(sacc[nt][0]), f2tf(sacc[nt][1]));
            *(uint2*)&Pbu[(m0 + r + 8) * PSTR + cc] =
                make_uint2(f2tf(sacc[nt][2]), f2tf(sacc[nt][3]));
        }
        __syncwarp();

        // ---- O += P @ V ----
        #pragma unroll
        for (int kk = 0; kk < 8; kk++) {
            const int kb2 = kk * 8;
            uint32_t pa[4];
            pa[0] = Pbu[(m0 + r) * PSTR + kb2 + cq];
            pa[1] = Pbu[(m0 + r + 8) * PSTR + kb2 + cq];
            pa[2] = Pbu[(m0 + r) * PSTR + kb2 + cq + 4];
            pa[3] = Pbu[(m0 + r + 8) * PSTR + kb2 + cq + 4];
            #pragma unroll
            for (int dt = 0; dt < 8; dt++) {
                const int col = dt * 8 + r;
                const uint32_t b0 = f2tf(Vs[(kb2 + cq) * VSTR + col]);
                const uint32_t b1 = f2tf(Vs[(kb2 + cq + 4) * VSTR + col]);
                mma_tf32(oacc[dt], pa, b0, b1);
            }
        }
    }

    // ---- normalize + store ----
    const float inv_lo = 1.0f / l_lo;
    const float inv_hi = 1.0f / l_hi;
    float* ob = O + ((size_t)(b * T_ + q0) * H_ + h) * D_;
    #pragma unroll
    for (int dt = 0; dt < 8; dt++) {
        const int cc = dt * 8 + cq * 2;
        *(float2*)(ob + (size_t)(m0 + r) * rowstride + cc) =
            make_float2(oacc[dt][0] * inv_lo, oacc[dt][1] * inv_lo);
        *(float2*)(ob + (size_t)(m0 + r + 8) * rowstride + cc) =
            make_float2(oacc[dt][2] * inv_hi, oacc[dt][3] * inv_hi);
    }
}

// ----------------------------------------------------------------------------
// Launch
// ----------------------------------------------------------------------------
extern "C" void kernel_launch(void* const* d_in, const int* in_sizes, int n_in,
                              void* d_out, int out_size)
{
    const float* x    = (const float*)d_in[0];
    const float* cosb = (const float*)d_in[1];
    const float* sinb = (const float*)d_in[2];
    const float* Wq   = (const float*)d_in[3];
    const float* Wk   = (const float*)d_in[4];
    const float* Wv   = (const float*)d_in[5];
    const float* Wp   = (const float*)d_in[6];
    float* out = (float*)d_out;

    float *q, *k, *v, *y;
    cudaGetSymbolAddress((void**)&q, g_q);
    cudaGetSymbolAddress((void**)&k, g_k);
    cudaGetSymbolAddress((void**)&v, g_v);
    cudaGetSymbolAddress((void**)&y, g_y);

    cudaFuncSetAttribute(gemm_tf32,
        cudaFuncAttributeMaxDynamicSharedMemorySize, GEMM_SMEM);
    cudaFuncSetAttribute(flash_tf32,
        cudaFuncAttributeMaxDynamicSharedMemorySize, FLASH_SMEM);

    dim3 ggrid(C_ / GBN, M_ / GBM);   // (8, 32)
    gemm_tf32<<<ggrid, 256, GEMM_SMEM>>>(x, Wq, q);
    gemm_tf32<<<ggrid, 256, GEMM_SMEM>>>(x, Wk, k);
    gemm_tf32<<<ggrid, 256, GEMM_SMEM>>>(x, Wv, v);

    rope_rms_kernel<<<(B_ * T_ * H_) / 8, 256>>>(q, k, cosb, sinb);

    dim3 fgrid(T_ / 128, H_, B_);     // (16, 16, 2)
    flash_tf32<<<fgrid, 256, FLASH_SMEM>>>(q, k, v, y);

    gemm_tf32<<<ggrid, 256, GEMM_SMEM>>>(y, Wp, out);
}

// round 6
// speedup vs baseline: 5.4640x; 1.8276x over previous
#include <cuda_runtime.h>
#include <cuda_fp16.h>
#include <math.h>
#include <stdint.h>

// Problem constants (B=2, T=2048, C=1024, H=16, D=64)
#define B_  2
#define T_  2048
#define C_  1024
#define H_  16
#define D_  64
#define M_  (B_*T_)        // 4096 rows

// Half scratch buffers
__device__ __half g_xh [M_*C_];
__device__ __half g_qh [M_*C_];
__device__ __half g_kh [M_*C_];
__device__ __half g_vh [M_*C_];
__device__ __half g_yh [M_*C_];
__device__ __half g_wqt[C_*C_];   // transposed [n][k] half
__device__ __half g_wkt[C_*C_];
__device__ __half g_wvt[C_*C_];
__device__ __half g_wpt[C_*C_];

// ----------------------------------------------------------------------------
// Helpers
// ----------------------------------------------------------------------------
__device__ __forceinline__ void mma_f16(float* c, const uint32_t* a,
                                        uint32_t b0, uint32_t b1) {
    asm volatile(
        "mma.sync.aligned.m16n8k16.row.col.f32.f16.f16.f32 "
        "{%0,%1,%2,%3}, {%4,%5,%6,%7}, {%8,%9}, {%0,%1,%2,%3};"
        : "+f"(c[0]), "+f"(c[1]), "+f"(c[2]), "+f"(c[3])
        : "r"(a[0]), "r"(a[1]), "r"(a[2]), "r"(a[3]), "r"(b0), "r"(b1));
}

__device__ __forceinline__ void cpasync16(void* s, const void* g) {
    uint32_t sp = (uint32_t)__cvta_generic_to_shared(s);
    asm volatile("cp.async.cg.shared.global [%0], [%1], 16;" :: "r"(sp), "l"(g));
}
#define CP_COMMIT() asm volatile("cp.async.commit_group;" ::: "memory")
template <int N> __device__ __forceinline__ void cp_wait() {
    asm volatile("cp.async.wait_group %0;" :: "n"(N) : "memory");
}

__device__ __forceinline__ uint32_t lds_u32(const __half* p) {
    return *(const uint32_t*)p;
}

__device__ __forceinline__ void ldsm_x4_t(uint32_t& r0, uint32_t& r1,
                                          uint32_t& r2, uint32_t& r3,
                                          uint32_t saddr) {
    asm volatile(
        "ldmatrix.sync.aligned.m8n8.x4.trans.shared.b16 {%0,%1,%2,%3}, [%4];"
        : "=r"(r0), "=r"(r1), "=r"(r2), "=r"(r3) : "r"(saddr));
}

// ----------------------------------------------------------------------------
// Pre-pass: x -> half ; W -> half transposed [n][k]
// ----------------------------------------------------------------------------
__global__ __launch_bounds__(256) void conv_xh(
    const float* __restrict__ in, __half* __restrict__ outp)
{
    const int i = blockIdx.x * 256 + threadIdx.x;
    float4 v = ((const float4*)in)[i];
    __half2 h0 = __floats2half2_rn(v.x, v.y);
    __half2 h1 = __floats2half2_rn(v.z, v.w);
    ((uint2*)outp)[i] = make_uint2(*(uint32_t*)&h0, *(uint32_t*)&h1);
}

__global__ __launch_bounds__(256) void trans_wh(
    const float* __restrict__ W, __half* __restrict__ Wt)
{
    __shared__ float t[32][33];
    const int tx = threadIdx.x & 31;
    const int ty = threadIdx.x >> 5;      // 0..7
    const int bx = blockIdx.x * 32;       // n block
    const int by = blockIdx.y * 32;       // k block
    #pragma unroll
    for (int i = ty; i < 32; i += 8)
        t[i][tx] = W[(size_t)(by + i) * C_ + bx + tx];   // t[k_loc][n_loc]
    __syncthreads();
    #pragma unroll
    for (int i = ty; i < 32; i += 8)
        Wt[(size_t)(bx + i) * C_ + by + tx] = __float2half(t[tx][i]);
}

// ----------------------------------------------------------------------------
// FP16 GEMM: D[m][n] = sum_k A[m][k] * Bt[n][k]; M=4096, N=K=1024.
// 128x128 tile, BK=64, 256 threads, cp.async double-buffered.
// Both smem tiles [row][k] half, stride 72 halfs (word stride 36 = 4 mod 32
// -> fragment address 4r+cq conflict-free).
// ----------------------------------------------------------------------------
#define GBM 128
#define GBN 128
#define GBK 64
#define GSTR 72
#define GNKT (C_/GBK)                         // 16
#define GSTAGE ((GBM + GBN) * GSTR)           // halfs per stage
#define GEMM_SMEM (2 * GSTAGE * 2)            // bytes = 73728

template<bool HOUT>
__global__ __launch_bounds__(256, 2) void gemm_h(
    const __half* __restrict__ A, const __half* __restrict__ Bt, void* Co)
{
    extern __shared__ __half hsm[];

    const int tid  = threadIdx.x;
    const int lane = tid & 31;
    const int wid  = tid >> 5;
    const int wm   = wid >> 1;       // 0..3
    const int wn   = wid & 1;        // 0..1
    const int bm = blockIdx.y * GBM;
    const int bn = blockIdx.x * GBN;
    const int r  = lane >> 2;        // 0..7
    const int cq = lane & 3;         // 0..3

    float acc[2][8][4];
    #pragma unroll
    for (int mt = 0; mt < 2; mt++)
        #pragma unroll
        for (int nt = 0; nt < 8; nt++)
            #pragma unroll
            for (int i = 0; i < 4; i++) acc[mt][nt][i] = 0.0f;

    // Per thread per stage: 4 A chunks + 4 B chunks (16B = 8 halfs each).
    #define GH_PREFETCH(kt, st)                                                \
    {                                                                          \
        __half* As_ = hsm + (st) * GSTAGE;                                     \
        __half* Bs_ = As_ + GBM * GSTR;                                        \
        const __half* Ag = A  + (size_t)bm * C_ + (kt) * GBK;                  \
        const __half* Bg = Bt + (size_t)bn * C_ + (kt) * GBK;                  \
        _Pragma("unroll")                                                      \
        for (int it = 0; it < 4; it++) {                                       \
            const int idx = it * 256 + tid;                                    \
            const int row = idx >> 3, g = (idx & 7) * 8;                       \
            cpasync16(As_ + row * GSTR + g, Ag + (size_t)row * C_ + g);        \
        }                                                                      \
        _Pragma("unroll")                                                      \
        for (int it = 0; it < 4; it++) {                                       \
            const int idx = it * 256 + tid;                                    \
            const int row = idx >> 3, g = (idx & 7) * 8;                       \
            cpasync16(Bs_ + row * GSTR + g, Bg + (size_t)row * C_ + g);        \
        }                                                                      \
    }

    GH_PREFETCH(0, 0);
    CP_COMMIT();

    for (int kt = 0; kt < GNKT; kt++) {
        if (kt + 1 < GNKT) {
            GH_PREFETCH(kt + 1, (kt + 1) & 1);
            CP_COMMIT();
            cp_wait<1>();
        } else {
            cp_wait<0>();
        }
        __syncthreads();

        const __half* As = hsm + (kt & 1) * GSTAGE;
        const __half* Bs = As + GBM * GSTR;

        #pragma unroll
        for (int kk = 0; kk < 4; kk++) {            // K=16 steps
            const int kb = kk * 16;
            uint32_t af[2][4];
            #pragma unroll
            for (int mt = 0; mt < 2; mt++) {
                const int row = wm * 32 + mt * 16 + r;
                af[mt][0] = lds_u32(&As[(size_t)row * GSTR + kb + 2*cq]);
                af[mt][1] = lds_u32(&As[(size_t)(row + 8) * GSTR + kb + 2*cq]);
                af[mt][2] = lds_u32(&As[(size_t)row * GSTR + kb + 8 + 2*cq]);
                af[mt][3] = lds_u32(&As[(size_t)(row + 8) * GSTR + kb + 8 + 2*cq]);
            }
            #pragma unroll
            for (int nt = 0; nt < 8; nt++) {
                const int col = wn * 64 + nt * 8 + r;
                const uint32_t b0 = lds_u32(&Bs[(size_t)col * GSTR + kb + 2*cq]);
                const uint32_t b1 = lds_u32(&Bs[(size_t)col * GSTR + kb + 8 + 2*cq]);
                mma_f16(acc[0][nt], af[0], b0, b1);
                mma_f16(acc[1][nt], af[1], b0, b1);
            }
        }
        __syncthreads();
    }

    // Epilogue: c0,c1 -> (row, 2cq..2cq+1); c2,c3 -> row+8
    #pragma unroll
    for (int mt = 0; mt < 2; mt++) {
        const int row = bm + wm * 32 + mt * 16 + r;
        #pragma unroll
        for (int nt = 0; nt < 8; nt++) {
            const int col = bn + wn * 64 + nt * 8 + cq * 2;
            if (HOUT) {
                __half* o = (__half*)Co;
                __half2 h0 = __floats2half2_rn(acc[mt][nt][0], acc[mt][nt][1]);
                __half2 h1 = __floats2half2_rn(acc[mt][nt][2], acc[mt][nt][3]);
                *(uint32_t*)(o + (size_t)row * C_ + col)       = *(uint32_t*)&h0;
                *(uint32_t*)(o + (size_t)(row + 8) * C_ + col) = *(uint32_t*)&h1;
            } else {
                float* o = (float*)Co;
                *(float2*)(o + (size_t)row * C_ + col) =
                    make_float2(acc[mt][nt][0], acc[mt][nt][1]);
                *(float2*)(o + (size_t)(row + 8) * C_ + col) =
                    make_float2(acc[mt][nt][2], acc[mt][nt][3]);
            }
        }
    }
}

// ----------------------------------------------------------------------------
// Fused RoPE + RMSNorm over half q and k. One warp per (b,t,h) row of D=64.
// ----------------------------------------------------------------------------
__global__ __launch_bounds__(256) void rope_rms_h(
    __half* __restrict__ q, __half* __restrict__ k,
    const float* __restrict__ cosb, const float* __restrict__ sinb)
{
    const int warp = threadIdx.x >> 5;
    const int lane = threadIdx.x & 31;
    const size_t row = (size_t)blockIdx.x * 8 + warp;   // (b*T + t)*H + h
    const int t = (int)((row / H_) % T_);

    const float c = cosb[t * D_ + lane];
    const float s = sinb[t * D_ + lane];

    #pragma unroll
    for (int w = 0; w < 2; w++) {
        __half* p = (w ? k : q) + row * D_;
        const float x1 = __half2float(p[lane]);
        const float x2 = __half2float(p[lane + 32]);
        const float y1 = x1 * c - x2 * s;
        const float y2 = x1 * s + x2 * c;
        float ss = y1 * y1 + y2 * y2;
        #pragma unroll
        for (int m = 16; m > 0; m >>= 1)
            ss += __shfl_xor_sync(0xffffffffu, ss, m);
        const float r = rsqrtf(ss * (1.0f / 64.0f) + 1e-6f);
        p[lane]      = __float2half(y1 * r);
        p[lane + 32] = __float2half(y2 * r);
    }
}

// ----------------------------------------------------------------------------
// Flash attention, fp16 mma, causal. 128-row q-tile, 64-row k-tiles, D=64.
// 256 threads (8 warps); warp w owns q rows [w*16, w*16+16).
// Pb: Q staging then P, [128][72] half (warp-private P rows).
// K/V cp.async double-buffered, natural [kpos][d] layout, stride 72.
// V B-fragments via ldmatrix.x4.trans (no transpose needed).
// ----------------------------------------------------------------------------
#define FSTRH 72
#define FLASH_SMEM ((128*FSTRH + 4*64*FSTRH) * 2)   // 55296 B

__global__ __launch_bounds__(256) void flash_h(
    const __half* __restrict__ Q, const __half* __restrict__ Kmat,
    const __half* __restrict__ V, __half* __restrict__ O)
{
    extern __shared__ __half fsm[];
    __half* Pb  = fsm;                       // [128][72]
    __half* Kb0 = fsm + 128 * FSTRH;
    __half* Kb1 = Kb0 + 64 * FSTRH;
    __half* Vb0 = Kb1 + 64 * FSTRH;
    __half* Vb1 = Vb0 + 64 * FSTRH;

    const int tid  = threadIdx.x;
    const int lane = tid & 31;
    const int warp = tid >> 5;         // 0..7
    const int r  = lane >> 2;          // 0..7
    const int cq = lane & 3;           // 0..3
    const int b = blockIdx.z, h = blockIdx.y;
    const int qi = (int)(gridDim.x - 1 - blockIdx.x);   // heavy blocks first
    const int q0 = qi * 128;
    const int m0 = warp * 16;

    const size_t rowstride = (size_t)H_ * D_;  // 1024 halfs

    const __half* kbase = Kmat + ((size_t)(b * T_) * H_ + h) * D_;
    const __half* vbase = V    + ((size_t)(b * T_) * H_ + h) * D_;

    // ldmatrix.trans per-lane source row decomposition
    const int lm_rr  = lane & 7;
    const int lm_sel = lane >> 3;                  // 0..3
    const int lm_kad = ((lm_sel & 1) << 3) + lm_rr;  // kpos offset within 16
    const int lm_dad = (lm_sel >> 1) << 3;           // d offset within 16

    // 64x64 half tile = 512 x 16B chunks -> 2 per thread per tensor
    #define KVH_PREFETCH(jt, Kbuf, Vbuf)                                       \
    {                                                                          \
        _Pragma("unroll")                                                      \
        for (int it = 0; it < 2; it++) {                                       \
            const int idx = it * 256 + tid;                                    \
            const int row = idx >> 3;             /* 0..63 */                  \
            const int g   = (idx & 7) * 8;        /* 0..56 */                  \
            const __half* kg = kbase + (size_t)((jt) * 64 + row) * rowstride;  \
            const __half* vg = vbase + (size_t)((jt) * 64 + row) * rowstride;  \
            cpasync16((Kbuf) + row * FSTRH + g, kg + g);                       \
            cpasync16((Vbuf) + row * FSTRH + g, vg + g);                       \
        }                                                                      \
    }

    // ---- Stage Q into Pb; prefetch K/V tile 0 ----
    const __half* qb = Q + ((size_t)(b * T_ + q0) * H_ + h) * D_;
    #pragma unroll
    for (int it = 0; it < 4; it++) {
        const int idx = it * 256 + tid;
        const int row = idx >> 3;                 // 0..127
        const int g   = (idx & 7) * 8;
        *(uint4*)&Pb[row * FSTRH + g] =
            *(const uint4*)(qb + (size_t)row * rowstride + g);
    }
    KVH_PREFETCH(0, Kb0, Vb0);
    CP_COMMIT();
    __syncthreads();

    // Q A-fragments: 4 k16 steps x 4 regs
    uint32_t qa[4][4];
    #pragma unroll
    for (int kk = 0; kk < 4; kk++) {
        const int kb = kk * 16;
        qa[kk][0] = lds_u32(&Pb[(m0 + r) * FSTRH + kb + 2*cq]);
        qa[kk][1] = lds_u32(&Pb[(m0 + r + 8) * FSTRH + kb + 2*cq]);
        qa[kk][2] = lds_u32(&Pb[(m0 + r) * FSTRH + kb + 8 + 2*cq]);
        qa[kk][3] = lds_u32(&Pb[(m0 + r + 8) * FSTRH + kb + 8 + 2*cq]);
    }
    __syncthreads();   // everyone has Q frags before Pb is reused for P

    float m_lo = -1e30f, m_hi = -1e30f, l_lo = 0.0f, l_hi = 0.0f;
    float oacc[8][4];
    #pragma unroll
    for (int dt = 0; dt < 8; dt++)
        #pragma unroll
        for (int i = 0; i < 4; i++) oacc[dt][i] = 0.0f;

    const int ntile = 2 * qi + 2;
    for (int jt = 0; jt < ntile; jt++) {
        if (jt + 1 < ntile) {
            if ((jt + 1) & 1) { KVH_PREFETCH(jt + 1, Kb1, Vb1); }
            else              { KVH_PREFETCH(jt + 1, Kb0, Vb0); }
            CP_COMMIT();
            cp_wait<1>();
        } else {
            cp_wait<0>();
        }
        __syncthreads();

        const __half* Ks = (jt & 1) ? Kb1 : Kb0;
        const __half* Vs = (jt & 1) ? Vb1 : Vb0;
        const uint32_t vs_u32 = (uint32_t)__cvta_generic_to_shared(Vs);
        const int k0 = jt * 64;

        // ---- S = Q @ K^T ----
        float sacc[8][4];
        #pragma unroll
        for (int nt = 0; nt < 8; nt++)
            #pragma unroll
            for (int i = 0; i < 4; i++) sacc[nt][i] = 0.0f;

        #pragma unroll
        for (int kk = 0; kk < 4; kk++) {
            const int kb2 = kk * 16;
            #pragma unroll
            for (int nt = 0; nt < 8; nt++) {
                const int col = nt * 8 + r;
                const uint32_t b0 = lds_u32(&Ks[col * FSTRH + kb2 + 2*cq]);
                const uint32_t b1 = lds_u32(&Ks[col * FSTRH + kb2 + 8 + 2*cq]);
                mma_f16(sacc[nt], qa[kk], b0, b1);
            }
        }

        // ---- scale (+ causal mask only on diagonal tiles) ----
        const int row_lo = q0 + m0 + r;
        const int row_hi = row_lo + 8;
        if (jt >= 2 * qi) {
            #pragma unroll
            for (int nt = 0; nt < 8; nt++) {
                const int c0 = k0 + nt * 8 + cq * 2;
                sacc[nt][0] = (row_lo >= c0    ) ? sacc[nt][0] * 0.125f : -1e30f;
                sacc[nt][1] = (row_lo >= c0 + 1) ? sacc[nt][1] * 0.125f : -1e30f;
                sacc[nt][2] = (row_hi >= c0    ) ? sacc[nt][2] * 0.125f : -1e30f;
                sacc[nt][3] = (row_hi >= c0 + 1) ? sacc[nt][3] * 0.125f : -1e30f;
            }
        } else {
            #pragma unroll
            for (int nt = 0; nt < 8; nt++) {
                sacc[nt][0] *= 0.125f; sacc[nt][1] *= 0.125f;
                sacc[nt][2] *= 0.125f; sacc[nt][3] *= 0.125f;
            }
        }

        // ---- online softmax (per-warp) ----
        float mt_lo = -1e30f, mt_hi = -1e30f;
        #pragma unroll
        for (int nt = 0; nt < 8; nt++) {
            mt_lo = fmaxf(mt_lo, fmaxf(sacc[nt][0], sacc[nt][1]));
            mt_hi = fmaxf(mt_hi, fmaxf(sacc[nt][2], sacc[nt][3]));
        }
        mt_lo = fmaxf(mt_lo, __shfl_xor_sync(0xffffffffu, mt_lo, 1));
        mt_lo = fmaxf(mt_lo, __shfl_xor_sync(0xffffffffu, mt_lo, 2));
        mt_hi = fmaxf(mt_hi, __shfl_xor_sync(0xffffffffu, mt_hi, 1));
        mt_hi = fmaxf(mt_hi, __shfl_xor_sync(0xffffffffu, mt_hi, 2));

        const float mn_lo = fmaxf(m_lo, mt_lo);
        const float mn_hi = fmaxf(m_hi, mt_hi);
        const float al_lo = __expf(m_lo - mn_lo);
        const float al_hi = __expf(m_hi - mn_hi);

        float rs_lo = 0.0f, rs_hi = 0.0f;
        #pragma unroll
        for (int nt = 0; nt < 8; nt++) {
            sacc[nt][0] = __expf(sacc[nt][0] - mn_lo);
            sacc[nt][1] = __expf(sacc[nt][1] - mn_lo);
            sacc[nt][2] = __expf(sacc[nt][2] - mn_hi);
            sacc[nt][3] = __expf(sacc[nt][3] - mn_hi);
            rs_lo += sacc[nt][0] + sacc[nt][1];
            rs_hi += sacc[nt][2] + sacc[nt][3];
        }
        rs_lo += __shfl_xor_sync(0xffffffffu, rs_lo, 1);
        rs_lo += __shfl_xor_sync(0xffffffffu, rs_lo, 2);
        rs_hi += __shfl_xor_sync(0xffffffffu, rs_hi, 1);
        rs_hi += __shfl_xor_sync(0xffffffffu, rs_hi, 2);

        l_lo = l_lo * al_lo + rs_lo;
        l_hi = l_hi * al_hi + rs_hi;
        m_lo = mn_lo; m_hi = mn_hi;
        #pragma unroll
        for (int dt = 0; dt < 8; dt++) {
            oacc[dt][0] *= al_lo; oacc[dt][1] *= al_lo;
            oacc[dt][2] *= al_hi; oacc[dt][3] *= al_hi;
        }

        // ---- write P (half pairs) to warp-private rows of Pb ----
        #pragma unroll
        for (int nt = 0; nt < 8; nt++) {
            const int cc = nt * 8 + cq * 2;
            __half2 p0 = __floats2half2_rn(sacc[nt][0], sacc[nt][1]);
            __half2 p1 = __floats2half2_rn(sacc[nt][2], sacc[nt][3]);
            *(uint32_t*)&Pb[(m0 + r) * FSTRH + cc]     = *(uint32_t*)&p0;
            *(uint32_t*)&Pb[(m0 + r + 8) * FSTRH + cc] = *(uint32_t*)&p1;
        }
        __syncwarp();

        // ---- O += P @ V (V B-frags via ldmatrix.x4.trans) ----
        #pragma unroll
        for (int kk = 0; kk < 4; kk++) {
            const int kb2 = kk * 16;
            uint32_t pa[4];
            pa[0] = lds_u32(&Pb[(m0 + r) * FSTRH + kb2 + 2*cq]);
            pa[1] = lds_u32(&Pb[(m0 + r + 8) * FSTRH + kb2 + 2*cq]);
            pa[2] = lds_u32(&Pb[(m0 + r) * FSTRH + kb2 + 8 + 2*cq]);
            pa[3] = lds_u32(&Pb[(m0 + r + 8) * FSTRH + kb2 + 8 + 2*cq]);
            #pragma unroll
            for (int dtp = 0; dtp < 4; dtp++) {
                uint32_t v0, v1, v2, v3;
                const uint32_t addr = vs_u32 +
                    (uint32_t)(((kb2 + lm_kad) * FSTRH + dtp * 16 + lm_dad) * 2);
                ldsm_x4_t(v0, v1, v2, v3, addr);
                mma_f16(oacc[2*dtp],     pa, v0, v1);
                mma_f16(oacc[2*dtp + 1], pa, v2, v3);
            }
        }
        __syncthreads();   // done reading K/V stage + P before next overwrite
    }

    // ---- normalize + store half ----
    const float inv_lo = 1.0f / l_lo;
    const float inv_hi = 1.0f / l_hi;
    __half* ob = O + ((size_t)(b * T_ + q0) * H_ + h) * D_;
    #pragma unroll
    for (int dt = 0; dt < 8; dt++) {
        const int cc = dt * 8 + cq * 2;
        __half2 h0 = __floats2half2_rn(oacc[dt][0] * inv_lo, oacc[dt][1] * inv_lo);
        __half2 h1 = __floats2half2_rn(oacc[dt][2] * inv_hi, oacc[dt][3] * inv_hi);
        *(uint32_t*)(ob + (size_t)(m0 + r) * rowstride + cc)     = *(uint32_t*)&h0;
        *(uint32_t*)(ob + (size_t)(m0 + r + 8) * rowstride + cc) = *(uint32_t*)&h1;
    }
}

// ----------------------------------------------------------------------------
// Launch
// ----------------------------------------------------------------------------
extern "C" void kernel_launch(void* const* d_in, const int* in_sizes, int n_in,
                              void* d_out, int out_size)
{
    const float* x    = (const float*)d_in[0];
    const float* cosb = (const float*)d_in[1];
    const float* sinb = (const float*)d_in[2];
    const float* Wq   = (const float*)d_in[3];
    const float* Wk   = (const float*)d_in[4];
    const float* Wv   = (const float*)d_in[5];
    const float* Wp   = (const float*)d_in[6];
    float* out = (float*)d_out;

    __half *xh, *qh, *kh, *vh, *yh, *wqt, *wkt, *wvt, *wpt;
    cudaGetSymbolAddress((void**)&xh,  g_xh);
    cudaGetSymbolAddress((void**)&qh,  g_qh);
    cudaGetSymbolAddress((void**)&kh,  g_kh);
    cudaGetSymbolAddress((void**)&vh,  g_vh);
    cudaGetSymbolAddress((void**)&yh,  g_yh);
    cudaGetSymbolAddress((void**)&wqt, g_wqt);
    cudaGetSymbolAddress((void**)&wkt, g_wkt);
    cudaGetSymbolAddress((void**)&wvt, g_wvt);
    cudaGetSymbolAddress((void**)&wpt, g_wpt);

    cudaFuncSetAttribute(gemm_h<true>,
        cudaFuncAttributeMaxDynamicSharedMemorySize, GEMM_SMEM);
    cudaFuncSetAttribute(gemm_h<false>,
        cudaFuncAttributeMaxDynamicSharedMemorySize, GEMM_SMEM);
    cudaFuncSetAttribute(flash_h,
        cudaFuncAttributeMaxDynamicSharedMemorySize, FLASH_SMEM);

    // Pre-pass
    conv_xh<<<(M_ * C_) / (256 * 4), 256>>>(x, xh);
    dim3 tgrid(C_ / 32, C_ / 32);
    trans_wh<<<tgrid, 256>>>(Wq, wqt);
    trans_wh<<<tgrid, 256>>>(Wk, wkt);
    trans_wh<<<tgrid, 256>>>(Wv, wvt);
    trans_wh<<<tgrid, 256>>>(Wp, wpt);

    dim3 ggrid(C_ / GBN, M_ / GBM);   // (8, 32)
    gemm_h<true><<<ggrid, 256, GEMM_SMEM>>>(xh, wqt, qh);
    gemm_h<true><<<ggrid, 256, GEMM_SMEM>>>(xh, wkt, kh);
    gemm_h<true><<<ggrid, 256, GEMM_SMEM>>>(xh, wvt, vh);

    rope_rms_h<<<(B_ * T_ * H_) / 8, 256>>>(qh, kh, cosb, sinb);

    dim3 fgrid(T_ / 128, H_, B_);     // (16, 16, 2)
    flash_h<<<fgrid, 256, FLASH_SMEM>>>(qh, kh, vh, yh);

    gemm_h<false><<<ggrid, 256, GEMM_SMEM>>>(yh, wpt, out);
}

// round 8
// speedup vs baseline: 5.7830x; 1.0584x over previous
#include <cuda_runtime.h>
#include <cuda_fp16.h>
#include <math.h>
#include <stdint.h>

// Problem constants (B=2, T=2048, C=1024, H=16, D=64)
#define B_  2
#define T_  2048
#define C_  1024
#define H_  16
#define D_  64
#define M_  (B_*T_)        // 4096 rows
#define N3  (3*C_)         // 3072

// Scratch
__device__ __half g_xh  [M_*C_];
__device__ __half g_qkv [M_*N3];     // [row][3072]: q | k | v
__device__ __half g_yh  [M_*C_];
__device__ __half g_wcat[N3*C_];     // transposed [n][k], q|k|v stacked
__device__ __half g_wpt [C_*C_];

// ----------------------------------------------------------------------------
// Helpers
// ----------------------------------------------------------------------------
__device__ __forceinline__ void mma_f16(float* c, const uint32_t* a,
                                        uint32_t b0, uint32_t b1) {
    asm volatile(
        "mma.sync.aligned.m16n8k16.row.col.f32.f16.f16.f32 "
        "{%0,%1,%2,%3}, {%4,%5,%6,%7}, {%8,%9}, {%0,%1,%2,%3};"
        : "+f"(c[0]), "+f"(c[1]), "+f"(c[2]), "+f"(c[3])
        : "r"(a[0]), "r"(a[1]), "r"(a[2]), "r"(a[3]), "r"(b0), "r"(b1));
}

__device__ __forceinline__ void cpasync16(void* s, const void* g) {
    uint32_t sp = (uint32_t)__cvta_generic_to_shared(s);
    asm volatile("cp.async.cg.shared.global [%0], [%1], 16;" :: "r"(sp), "l"(g));
}
#define CP_COMMIT() asm volatile("cp.async.commit_group;" ::: "memory")
template <int N> __device__ __forceinline__ void cp_wait() {
    asm volatile("cp.async.wait_group %0;" :: "n"(N) : "memory");
}

__device__ __forceinline__ void ldsm_x4(uint32_t& r0, uint32_t& r1,
                                        uint32_t& r2, uint32_t& r3,
                                        uint32_t saddr) {
    asm volatile(
        "ldmatrix.sync.aligned.m8n8.x4.shared.b16 {%0,%1,%2,%3}, [%4];"
        : "=r"(r0), "=r"(r1), "=r"(r2), "=r"(r3) : "r"(saddr));
}
__device__ __forceinline__ void ldsm_x4_t(uint32_t& r0, uint32_t& r1,
                                          uint32_t& r2, uint32_t& r3,
                                          uint32_t saddr) {
    asm volatile(
        "ldmatrix.sync.aligned.m8n8.x4.trans.shared.b16 {%0,%1,%2,%3}, [%4];"
        : "=r"(r0), "=r"(r1), "=r"(r2), "=r"(r3) : "r"(saddr));
}

__device__ __forceinline__ uint32_t lds_u32(const __half* p) {
    return *(const uint32_t*)p;
}

// ----------------------------------------------------------------------------
// Pre-pass: x -> half ; all 4 weights -> half transposed [n][k] (one kernel)
// ----------------------------------------------------------------------------
__global__ __launch_bounds__(256) void conv_xh(
    const float* __restrict__ in, __half* __restrict__ outp)
{
    const int i = blockIdx.x * 256 + threadIdx.x;
    float4 v = ((const float4*)in)[i];
    __half2 h0 = __floats2half2_rn(v.x, v.y);
    __half2 h1 = __floats2half2_rn(v.z, v.w);
    ((uint2*)outp)[i] = make_uint2(*(uint32_t*)&h0, *(uint32_t*)&h1);
}

__global__ __launch_bounds__(256) void trans_all(
    const float* __restrict__ Wq, const float* __restrict__ Wk,
    const float* __restrict__ Wv, const float* __restrict__ Wp,
    __half* __restrict__ wcat, __half* __restrict__ wpt)
{
    __shared__ float t[32][33];
    const int z = blockIdx.z;
    const float* W = (z == 0) ? Wq : (z == 1) ? Wk : (z == 2) ? Wv : Wp;
    __half* Wt = (z < 3) ? (wcat + (size_t)z * C_ * C_) : wpt;

    const int tx = threadIdx.x & 31;
    const int ty = threadIdx.x >> 5;
    const int bx = blockIdx.x * 32;       // n block
    const int by = blockIdx.y * 32;       // k block
    #pragma unroll
    for (int i = ty; i < 32; i += 8)
        t[i][tx] = W[(size_t)(by + i) * C_ + bx + tx];
    __syncthreads();
    #pragma unroll
    for (int i = ty; i < 32; i += 8)
        Wt[(size_t)(bx + i) * C_ + by + tx] = __float2half(t[tx][i]);
}

// ----------------------------------------------------------------------------
// FP16 GEMM, ldmatrix fragments. D[m][n] = sum_k A[m][k]*Bt[n][k].
// MODE 1: N=3072, half out stride 3072, fused RoPE+RMSNorm on cols<2048.
// MODE 0: N=1024, fp32 out stride 1024.
// 128x128 tile, BK=64, 256 threads, cp.async double-buffered, stride 72 halfs.
// ----------------------------------------------------------------------------
#define GBM 128
#define GBN 128
#define GBK 64
#define GSTR 72
#define GNKT (C_/GBK)                         // 16
#define GSTAGE ((GBM + GBN) * GSTR)           // halfs per stage
#define GEMM_SMEM (2 * GSTAGE * 2)            // 73728 B

template<int MODE>
__global__ __launch_bounds__(256, 2) void gemm2(
    const __half* __restrict__ A, const __half* __restrict__ Bt, void* Co,
    const float* __restrict__ cosb, const float* __restrict__ sinb)
{
    extern __shared__ __half hsm[];
    constexpr int OSTR = MODE ? N3 : C_;

    const int tid  = threadIdx.x;
    const int lane = tid & 31;
    const int wid  = tid >> 5;
    const int wm   = wid >> 1;       // 0..3
    const int wn   = wid & 1;        // 0..1
    const int bm = blockIdx.y * GBM;
    const int bn = blockIdx.x * GBN;
    const int r  = lane >> 2;        // 0..7
    const int cq = lane & 3;         // 0..3

    // ldmatrix per-lane address offset (same formula for A- and B-type):
    // row' = base + ((lane>>3)&1)*8 + (lane&7), k' = kb + (lane>>4)*8
    const int lm_off = ((((lane >> 3) & 1) * 8 + (lane & 7)) * GSTR
                        + (lane >> 4) * 8) * 2;   // bytes

    float acc[2][8][4];
    #pragma unroll
    for (int mt = 0; mt < 2; mt++)
        #pragma unroll
        for (int nt = 0; nt < 8; nt++)
            #pragma unroll
            for (int i = 0; i < 4; i++) acc[mt][nt][i] = 0.0f;

    #define GH_PREFETCH(kt, st)                                                \
    {                                                                          \
        __half* As_ = hsm + (st) * GSTAGE;                                     \
        __half* Bs_ = As_ + GBM * GSTR;                                        \
        const __half* Ag = A  + (size_t)bm * C_ + (kt) * GBK;                  \
        const __half* Bg = Bt + (size_t)bn * C_ + (kt) * GBK;                  \
        _Pragma("unroll")                                                      \
        for (int it = 0; it < 4; it++) {                                       \
            const int idx = it * 256 + tid;                                    \
            const int row = idx >> 3, g = (idx & 7) * 8;                       \
            cpasync16(As_ + row * GSTR + g, Ag + (size_t)row * C_ + g);        \
        }                                                                      \
        _Pragma("unroll")                                                      \
        for (int it = 0; it < 4; it++) {                                       \
            const int idx = it * 256 + tid;                                    \
            const int row = idx >> 3, g = (idx & 7) * 8;                       \
            cpasync16(Bs_ + row * GSTR + g, Bg + (size_t)row * C_ + g);        \
        }                                                                      \
    }

    GH_PREFETCH(0, 0);
    CP_COMMIT();

    for (int kt = 0; kt < GNKT; kt++) {
        if (kt + 1 < GNKT) {
            GH_PREFETCH(kt + 1, (kt + 1) & 1);
            CP_COMMIT();
            cp_wait<1>();
        } else {
            cp_wait<0>();
        }
        __syncthreads();

        const __half* As = hsm + (kt & 1) * GSTAGE;
        const __half* Bs = As + GBM * GSTR;
        const uint32_t as_u = (uint32_t)__cvta_generic_to_shared(As) + lm_off;
        const uint32_t bs_u = (uint32_t)__cvta_generic_to_shared(Bs) + lm_off;

        #pragma unroll
        for (int kk = 0; kk < 4; kk++) {            // K=16 steps
            const int kb = kk * 16;
            uint32_t af[2][4];
            #pragma unroll
            for (int mt = 0; mt < 2; mt++)
                ldsm_x4(af[mt][0], af[mt][1], af[mt][2], af[mt][3],
                        as_u + ((wm * 32 + mt * 16) * GSTR + kb) * 2);
            #pragma unroll
            for (int ntp = 0; ntp < 4; ntp++) {
                uint32_t b0e, b0o, b1e, b1o;
                ldsm_x4(b0e, b0o, b1e, b1o,
                        bs_u + ((wn * 64 + ntp * 16) * GSTR + kb) * 2);
                mma_f16(acc[0][2*ntp],     af[0], b0e, b1e);
                mma_f16(acc[0][2*ntp + 1], af[0], b0o, b1o);
                mma_f16(acc[1][2*ntp],     af[1], b0e, b1e);
                mma_f16(acc[1][2*ntp + 1], af[1], b0o, b1o);
            }
        }
        __syncthreads();
    }

    // ---- Epilogue ----
    if (MODE == 0) {
        float* o = (float*)Co;
        #pragma unroll
        for (int mt = 0; mt < 2; mt++) {
            const int row = bm + wm * 32 + mt * 16 + r;
            #pragma unroll
            for (int nt = 0; nt < 8; nt++) {
                const int col = bn + wn * 64 + nt * 8 + cq * 2;
                *(float2*)(o + (size_t)row * OSTR + col) =
                    make_float2(acc[mt][nt][0], acc[mt][nt][1]);
                *(float2*)(o + (size_t)(row + 8) * OSTR + col) =
                    make_float2(acc[mt][nt][2], acc[mt][nt][3]);
            }
        }
    } else {
        // Fused RoPE + RMSNorm for q/k cols (<2048); v passes through.
        __half* o = (__half*)Co;
        const bool is_v = (bn + wn * 64) >= 2048;
        #pragma unroll
        for (int mt = 0; mt < 2; mt++) {
            #pragma unroll
            for (int rh = 0; rh < 2; rh++) {      // c0,c1 = row r; c2,c3 = r+8
                const int row = bm + wm * 32 + mt * 16 + r + rh * 8;
                const int i0 = rh * 2, i1 = rh * 2 + 1;
                float ov[8][2];
                if (!is_v) {
                    const int t = row & (T_ - 1);
                    float ssum = 0.0f;
                    #pragma unroll
                    for (int nt = 0; nt < 4; nt++) {
                        const int d0 = nt * 8 + cq * 2;
                        const float2 cc = *(const float2*)&cosb[(size_t)t * D_ + d0];
                        const float2 sn = *(const float2*)&sinb[(size_t)t * D_ + d0];
                        const float x1a = acc[mt][nt][i0],     x1b = acc[mt][nt][i1];
                        const float x2a = acc[mt][nt + 4][i0], x2b = acc[mt][nt + 4][i1];
                        ov[nt][0]     = x1a * cc.x - x2a * sn.x;
                        ov[nt][1]     = x1b * cc.y - x2b * sn.y;
                        ov[nt + 4][0] = x1a * sn.x + x2a * cc.x;
                        ov[nt + 4][1] = x1b * sn.y + x2b * cc.y;
                        ssum += ov[nt][0]*ov[nt][0] + ov[nt][1]*ov[nt][1]
                              + ov[nt+4][0]*ov[nt+4][0] + ov[nt+4][1]*ov[nt+4][1];
                    }
                    ssum += __shfl_xor_sync(0xffffffffu, ssum, 1);
                    ssum += __shfl_xor_sync(0xffffffffu, ssum, 2);
                    const float rinv = rsqrtf(ssum * (1.0f / 64.0f) + 1e-6f);
                    #pragma unroll
                    for (int nt = 0; nt < 8; nt++) {
                        ov[nt][0] *= rinv; ov[nt][1] *= rinv;
                    }
                } else {
                    #pragma unroll
                    for (int nt = 0; nt < 8; nt++) {
                        ov[nt][0] = acc[mt][nt][i0];
                        ov[nt][1] = acc[mt][nt][i1];
                    }
                }
                #pragma unroll
                for (int nt = 0; nt < 8; nt++) {
                    const int col = bn + wn * 64 + nt * 8 + cq * 2;
                    __half2 hv = __floats2half2_rn(ov[nt][0], ov[nt][1]);
                    *(uint32_t*)(o + (size_t)row * OSTR + col) = *(uint32_t*)&hv;
                }
            }
        }
    }
}

// ----------------------------------------------------------------------------
// Flash attention, fp16 mma + ldmatrix, causal. 128-row q-tile, 64-row k-tile.
// QKV packed buffer [row][3072]: q | k | v. Output yh [row][1024].
// ----------------------------------------------------------------------------
#define FSTRH 72
#define FLASH_SMEM ((128*FSTRH + 4*64*FSTRH) * 2)   // 55296 B

__global__ __launch_bounds__(256) void flash_h(
    const __half* __restrict__ QKV, __half* __restrict__ O)
{
    extern __shared__ __half fsm[];
    __half* Pb  = fsm;                       // [128][72]
    __half* Kb0 = fsm + 128 * FSTRH;
    __half* Kb1 = Kb0 + 64 * FSTRH;
    __half* Vb0 = Kb1 + 64 * FSTRH;
    __half* Vb1 = Vb0 + 64 * FSTRH;
    const uint32_t pb_u = (uint32_t)__cvta_generic_to_shared(Pb);

    const int tid  = threadIdx.x;
    const int lane = tid & 31;
    const int warp = tid >> 5;         // 0..7
    const int r  = lane >> 2;          // 0..7
    const int cq = lane & 3;           // 0..3
    const int b = blockIdx.z, h = blockIdx.y;
    const int qi = (int)(gridDim.x - 1 - blockIdx.x);   // heavy blocks first
    const int q0 = qi * 128;
    const int m0 = warp * 16;

    const size_t rowstride = N3;           // 3072 halfs

    const int lm_off = ((((lane >> 3) & 1) * 8 + (lane & 7)) * FSTRH
                        + (lane >> 4) * 8) * 2;   // bytes (A/B-type ldmatrix)

    // trans-ldmatrix (V) per-lane decomposition
    const int lm_rr  = lane & 7;
    const int lm_sel = lane >> 3;
    const int lm_kad = ((lm_sel & 1) << 3) + lm_rr;
    const int lm_dad = (lm_sel >> 1) << 3;

    const __half* kbase = QKV + (size_t)(b * T_) * rowstride + C_   + h * D_;
    const __half* vbase = QKV + (size_t)(b * T_) * rowstride + 2*C_ + h * D_;

    #define KVH_PREFETCH(jt, Kbuf, Vbuf)                                       \
    {                                                                          \
        _Pragma("unroll")                                                      \
        for (int it = 0; it < 2; it++) {                                       \
            const int idx = it * 256 + tid;                                    \
            const int row = idx >> 3;                                          \
            const int g   = (idx & 7) * 8;                                     \
            const __half* kg = kbase + (size_t)((jt) * 64 + row) * rowstride;  \
            const __half* vg = vbase + (size_t)((jt) * 64 + row) * rowstride;  \
            cpasync16((Kbuf) + row * FSTRH + g, kg + g);                       \
            cpasync16((Vbuf) + row * FSTRH + g, vg + g);                       \
        }                                                                      \
    }

    // ---- Stage Q into Pb; prefetch K/V tile 0 ----
    const __half* qb = QKV + (size_t)(b * T_ + q0) * rowstride + h * D_;
    #pragma unroll
    for (int it = 0; it < 4; it++) {
        const int idx = it * 256 + tid;
        const int row = idx >> 3;
        const int g   = (idx & 7) * 8;
        *(uint4*)&Pb[row * FSTRH + g] =
            *(const uint4*)(qb + (size_t)row * rowstride + g);
    }
    KVH_PREFETCH(0, Kb0, Vb0);
    CP_COMMIT();
    __syncthreads();

    uint32_t qa[4][4];
    #pragma unroll
    for (int kk = 0; kk < 4; kk++)
        ldsm_x4(qa[kk][0], qa[kk][1], qa[kk][2], qa[kk][3],
                pb_u + (m0 * FSTRH + kk * 16) * 2 + lm_off);
    __syncthreads();   // Q frags secured before Pb reused for P

    float m_lo = -1e30f, m_hi = -1e30f, l_lo = 0.0f, l_hi = 0.0f;
    float oacc[8][4];
    #pragma unroll
    for (int dt = 0; dt < 8; dt++)
        #pragma unroll
        for (int i = 0; i < 4; i++) oacc[dt][i] = 0.0f;

    const int ntile = 2 * qi + 2;
    for (int jt = 0; jt < ntile; jt++) {
        if (jt + 1 < ntile) {
            if ((jt + 1) & 1) { KVH_PREFETCH(jt + 1, Kb1, Vb1); }
            else              { KVH_PREFETCH(jt + 1, Kb0, Vb0); }
            CP_COMMIT();
            cp_wait<1>();
        } else {
            cp_wait<0>();
        }
        __syncthreads();

        const __half* Ks = (jt & 1) ? Kb1 : Kb0;
        const __half* Vs = (jt & 1) ? Vb1 : Vb0;
        const uint32_t ks_u = (uint32_t)__cvta_generic_to_shared(Ks) + lm_off;
        const uint32_t vs_u = (uint32_t)__cvta_generic_to_shared(Vs);
        const int k0 = jt * 64;

        // ---- S = Q @ K^T ----
        float sacc[8][4];
        #pragma unroll
        for (int nt = 0; nt < 8; nt++)
            #pragma unroll
            for (int i = 0; i < 4; i++) sacc[nt][i] = 0.0f;

        #pragma unroll
        for (int kk = 0; kk < 4; kk++) {
            const int kb2 = kk * 16;
            #pragma unroll
            for (int ntp = 0; ntp < 4; ntp++) {
                uint32_t b0e, b0o, b1e, b1o;
                ldsm_x4(b0e, b0o, b1e, b1o,
                        ks_u + (ntp * 16 * FSTRH + kb2) * 2);
                mma_f16(sacc[2*ntp],     qa[kk], b0e, b1e);
                mma_f16(sacc[2*ntp + 1], qa[kk], b0o, b1o);
            }
        }

        // ---- scale (+ causal mask only on diagonal tiles) ----
        const int row_lo = q0 + m0 + r;
        const int row_hi = row_lo + 8;
        if (jt >= 2 * qi) {
            #pragma unroll
            for (int nt = 0; nt < 8; nt++) {
                const int c0 = k0 + nt * 8 + cq * 2;
                sacc[nt][0] = (row_lo >= c0    ) ? sacc[nt][0] * 0.125f : -1e30f;
                sacc[nt][1] = (row_lo >= c0 + 1) ? sacc[nt][1] * 0.125f : -1e30f;
                sacc[nt][2] = (row_hi >= c0    ) ? sacc[nt][2] * 0.125f : -1e30f;
                sacc[nt][3] = (row_hi >= c0 + 1) ? sacc[nt][3] * 0.125f : -1e30f;
            }
        } else {
            #pragma unroll
            for (int nt = 0; nt < 8; nt++) {
                sacc[nt][0] *= 0.125f; sacc[nt][1] *= 0.125f;
                sacc[nt][2] *= 0.125f; sacc[nt][3] *= 0.125f;
            }
        }

        // ---- online softmax (per-warp) ----
        float mt_lo = -1e30f, mt_hi = -1e30f;
        #pragma unroll
        for (int nt = 0; nt < 8; nt++) {
            mt_lo = fmaxf(mt_lo, fmaxf(sacc[nt][0], sacc[nt][1]));
            mt_hi = fmaxf(mt_hi, fmaxf(sacc[nt][2], sacc[nt][3]));
        }
        mt_lo = fmaxf(mt_lo, __shfl_xor_sync(0xffffffffu, mt_lo, 1));
        mt_lo = fmaxf(mt_lo, __shfl_xor_sync(0xffffffffu, mt_lo, 2));
        mt_hi = fmaxf(mt_hi, __shfl_xor_sync(0xffffffffu, mt_hi, 1));
        mt_hi = fmaxf(mt_hi, __shfl_xor_sync(0xffffffffu, mt_hi, 2));

        const float mn_lo = fmaxf(m_lo, mt_lo);
        const float mn_hi = fmaxf(m_hi, mt_hi);
        const float al_lo = __expf(m_lo - mn_lo);
        const float al_hi = __expf(m_hi - mn_hi);

        float rs_lo = 0.0f, rs_hi = 0.0f;
        #pragma unroll
        for (int nt = 0; nt < 8; nt++) {
            sacc[nt][0] = __expf(sacc[nt][0] - mn_lo);
            sacc[nt][1] = __expf(sacc[nt][1] - mn_lo);
            sacc[nt][2] = __expf(sacc[nt][2] - mn_hi);
            sacc[nt][3] = __expf(sacc[nt][3] - mn_hi);
            rs_lo += sacc[nt][0] + sacc[nt][1];
            rs_hi += sacc[nt][2] + sacc[nt][3];
        }
        rs_lo += __shfl_xor_sync(0xffffffffu, rs_lo, 1);
        rs_lo += __shfl_xor_sync(0xffffffffu, rs_lo, 2);
        rs_hi += __shfl_xor_sync(0xffffffffu, rs_hi, 1);
        rs_hi += __shfl_xor_sync(0xffffffffu, rs_hi, 2);

        l_lo = l_lo * al_lo + rs_lo;
        l_hi = l_hi * al_hi + rs_hi;
        m_lo = mn_lo; m_hi = mn_hi;
        #pragma unroll
        for (int dt = 0; dt < 8; dt++) {
            oacc[dt][0] *= al_lo; oacc[dt][1] *= al_lo;
            oacc[dt][2] *= al_hi; oacc[dt][3] *= al_hi;
        }

        // ---- write P (half pairs) to warp-private rows of Pb ----
        #pragma unroll
        for (int nt = 0; nt < 8; nt++) {
            const int cc = nt * 8 + cq * 2;
            __half2 p0 = __floats2half2_rn(sacc[nt][0], sacc[nt][1]);
            __half2 p1 = __floats2half2_rn(sacc[nt][2], sacc[nt][3]);
            *(uint32_t*)&Pb[(m0 + r) * FSTRH + cc]     = *(uint32_t*)&p0;
            *(uint32_t*)&Pb[(m0 + r + 8) * FSTRH + cc] = *(uint32_t*)&p1;
        }
        __syncwarp();

        // ---- O += P @ V ----
        #pragma unroll
        for (int kk = 0; kk < 4; kk++) {
            const int kb2 = kk * 16;
            uint32_t pa[4];
            ldsm_x4(pa[0], pa[1], pa[2], pa[3],
                    pb_u + (m0 * FSTRH + kb2) * 2 + lm_off);
            #pragma unroll
            for (int dtp = 0; dtp < 4; dtp++) {
                uint32_t v0, v1, v2, v3;
                const uint32_t addr = vs_u +
                    (uint32_t)(((kb2 + lm_kad) * FSTRH + dtp * 16 + lm_dad) * 2);
                ldsm_x4_t(v0, v1, v2, v3, addr);
                mma_f16(oacc[2*dtp],     pa, v0, v1);
                mma_f16(oacc[2*dtp + 1], pa, v2, v3);
            }
        }
        __syncthreads();   // done reading K/V stage + P before next overwrite
    }

    // ---- normalize + store half (stride 1024) ----
    const float inv_lo = 1.0f / l_lo;
    const float inv_hi = 1.0f / l_hi;
    __half* ob = O + ((size_t)(b * T_ + q0) * H_ + h) * D_;
    #pragma unroll
    for (int dt = 0; dt < 8; dt++) {
        const int cc = dt * 8 + cq * 2;
        __half2 h0 = __floats2half2_rn(oacc[dt][0] * inv_lo, oacc[dt][1] * inv_lo);
        __half2 h1 = __floats2half2_rn(oacc[dt][2] * inv_hi, oacc[dt][3] * inv_hi);
        *(uint32_t*)(ob + (size_t)(m0 + r) * C_ + cc)     = *(uint32_t*)&h0;
        *(uint32_t*)(ob + (size_t)(m0 + r + 8) * C_ + cc) = *(uint32_t*)&h1;
    }
}

// ----------------------------------------------------------------------------
// Launch
// ----------------------------------------------------------------------------
extern "C" void kernel_launch(void* const* d_in, const int* in_sizes, int n_in,
                              void* d_out, int out_size)
{
    const float* x    = (const float*)d_in[0];
    const float* cosb = (const float*)d_in[1];
    const float* sinb = (const float*)d_in[2];
    const float* Wq   = (const float*)d_in[3];
    const float* Wk   = (const float*)d_in[4];
    const float* Wv   = (const float*)d_in[5];
    const float* Wp   = (const float*)d_in[6];
    float* out = (float*)d_out;

    __half *xh, *qkv, *yh, *wcat, *wpt;
    cudaGetSymbolAddress((void**)&xh,   g_xh);
    cudaGetSymbolAddress((void**)&qkv,  g_qkv);
    cudaGetSymbolAddress((void**)&yh,   g_yh);
    cudaGetSymbolAddress((void**)&wcat, g_wcat);
    cudaGetSymbolAddress((void**)&wpt,  g_wpt);

    cudaFuncSetAttribute(gemm2<1>,
        cudaFuncAttributeMaxDynamicSharedMemorySize, GEMM_SMEM);
    cudaFuncSetAttribute(gemm2<0>,
        cudaFuncAttributeMaxDynamicSharedMemorySize, GEMM_SMEM);
    cudaFuncSetAttribute(flash_h,
        cudaFuncAttributeMaxDynamicSharedMemorySize, FLASH_SMEM);

    // Pre-pass
    conv_xh<<<(M_ * C_) / (256 * 4), 256>>>(x, xh);
    dim3 tgrid(C_ / 32, C_ / 32, 4);
    trans_all<<<tgrid, 256>>>(Wq, Wk, Wv, Wp, wcat, wpt);

    // Fused QKV projection + RoPE + RMSNorm
    dim3 qgrid(N3 / GBN, M_ / GBM);   // (24, 32)
    gemm2<1><<<qgrid, 256, GEMM_SMEM>>>(xh, wcat, qkv, cosb, sinb);

    // Attention
    dim3 fgrid(T_ / 128, H_, B_);     // (16, 16, 2)
    flash_h<<<fgrid, 256, FLASH_SMEM>>>(qkv, yh);

    // Output projection (fp32 out)
    dim3 pgrid(C_ / GBN, M_ / GBM);   // (8, 32)
    gemm2<0><<<pgrid, 256, GEMM_SMEM>>>(yh, wpt, out, cosb, sinb);
}

// round 10
// speedup vs baseline: 6.5402x; 1.1309x over previous
#include <cuda_runtime.h>
#include <cuda_fp16.h>
#include <math.h>
#include <stdint.h>

// Problem constants (B=2, T=2048, C=1024, H=16, D=64)
#define B_  2
#define T_  2048
#define C_  1024
#define H_  16
#define D_  64
#define M_  (B_*T_)        // 4096 rows
#define N3  (3*C_)         // 3072

// Scratch
__device__ __half g_xh  [M_*C_];
__device__ __half g_qkv [M_*N3];     // [row][3072]: q | k | v
__device__ __half g_yh  [M_*C_];
__device__ __half g_wcat[N3*C_];     // transposed [n][k], q|k|v stacked
__device__ __half g_wpt [C_*C_];

// ----------------------------------------------------------------------------
// Helpers
// ----------------------------------------------------------------------------
__device__ __forceinline__ void mma_f16(float* c, const uint32_t* a,
                                        uint32_t b0, uint32_t b1) {
    asm volatile(
        "mma.sync.aligned.m16n8k16.row.col.f32.f16.f16.f32 "
        "{%0,%1,%2,%3}, {%4,%5,%6,%7}, {%8,%9}, {%0,%1,%2,%3};"
        : "+f"(c[0]), "+f"(c[1]), "+f"(c[2]), "+f"(c[3])
        : "r"(a[0]), "r"(a[1]), "r"(a[2]), "r"(a[3]), "r"(b0), "r"(b1));
}

__device__ __forceinline__ void cpasync16(void* s, const void* g) {
    uint32_t sp = (uint32_t)__cvta_generic_to_shared(s);
    asm volatile("cp.async.cg.shared.global [%0], [%1], 16;" :: "r"(sp), "l"(g));
}
#define CP_COMMIT() asm volatile("cp.async.commit_group;" ::: "memory")
template <int N> __device__ __forceinline__ void cp_wait() {
    asm volatile("cp.async.wait_group %0;" :: "n"(N) : "memory");
}

__device__ __forceinline__ void ldsm_x4(uint32_t& r0, uint32_t& r1,
                                        uint32_t& r2, uint32_t& r3,
                                        uint32_t saddr) {
    asm volatile(
        "ldmatrix.sync.aligned.m8n8.x4.shared.b16 {%0,%1,%2,%3}, [%4];"
        : "=r"(r0), "=r"(r1), "=r"(r2), "=r"(r3) : "r"(saddr));
}
__device__ __forceinline__ void ldsm_x4_t(uint32_t& r0, uint32_t& r1,
                                          uint32_t& r2, uint32_t& r3,
                                          uint32_t saddr) {
    asm volatile(
        "ldmatrix.sync.aligned.m8n8.x4.trans.shared.b16 {%0,%1,%2,%3}, [%4];"
        : "=r"(r0), "=r"(r1), "=r"(r2), "=r"(r3) : "r"(saddr));
}

__device__ __forceinline__ float ex2f(float x) {
    float y;
    asm("ex2.approx.ftz.f32 %0, %1;" : "=f"(y) : "f"(x));
    return y;
}

__device__ __forceinline__ uint32_t packh2(float a, float b) {
    __half2 h = __floats2half2_rn(a, b);
    return *(uint32_t*)&h;
}

// ----------------------------------------------------------------------------
// Pre-pass: x -> half ; all 4 weights -> half transposed [n][k] (one kernel)
// ----------------------------------------------------------------------------
__global__ __launch_bounds__(256) void conv_xh(
    const float* __restrict__ in, __half* __restrict__ outp)
{
    const int i = blockIdx.x * 256 + threadIdx.x;
    float4 v = ((const float4*)in)[i];
    __half2 h0 = __floats2half2_rn(v.x, v.y);
    __half2 h1 = __floats2half2_rn(v.z, v.w);
    ((uint2*)outp)[i] = make_uint2(*(uint32_t*)&h0, *(uint32_t*)&h1);
}

__global__ __launch_bounds__(256) void trans_all(
    const float* __restrict__ Wq, const float* __restrict__ Wk,
    const float* __restrict__ Wv, const float* __restrict__ Wp,
    __half* __restrict__ wcat, __half* __restrict__ wpt)
{
    __shared__ float t[32][33];
    const int z = blockIdx.z;
    const float* W = (z == 0) ? Wq : (z == 1) ? Wk : (z == 2) ? Wv : Wp;
    __half* Wt = (z < 3) ? (wcat + (size_t)z * C_ * C_) : wpt;

    const int tx = threadIdx.x & 31;
    const int ty = threadIdx.x >> 5;
    const int bx = blockIdx.x * 32;       // n block
    const int by = blockIdx.y * 32;       // k block
    #pragma unroll
    for (int i = ty; i < 32; i += 8)
        t[i][tx] = W[(size_t)(by + i) * C_ + bx + tx];
    __syncthreads();
    #pragma unroll
    for (int i = ty; i < 32; i += 8)
        Wt[(size_t)(bx + i) * C_ + by + tx] = __float2half(t[tx][i]);
}

// ----------------------------------------------------------------------------
// FP16 GEMM, ldmatrix fragments. D[m][n] = sum_k A[m][k]*Bt[n][k].
// MODE 1: N=3072, half out stride 3072, fused RoPE+RMSNorm on cols<2048.
// MODE 0: N=1024, fp32 out stride 1024.
// ----------------------------------------------------------------------------
#define GBM 128
#define GBN 128
#define GBK 64
#define GSTR 72
#define GNKT (C_/GBK)                         // 16
#define GSTAGE ((GBM + GBN) * GSTR)           // halfs per stage
#define GEMM_SMEM (2 * GSTAGE * 2)            // 73728 B

template<int MODE>
__global__ __launch_bounds__(256, 2) void gemm2(
    const __half* __restrict__ A, const __half* __restrict__ Bt, void* Co,
    const float* __restrict__ cosb, const float* __restrict__ sinb)
{
    extern __shared__ __half hsm[];
    constexpr int OSTR = MODE ? N3 : C_;

    const int tid  = threadIdx.x;
    const int lane = tid & 31;
    const int wid  = tid >> 5;
    const int wm   = wid >> 1;       // 0..3
    const int wn   = wid & 1;        // 0..1
    const int bm = blockIdx.y * GBM;
    const int bn = blockIdx.x * GBN;
    const int r  = lane >> 2;        // 0..7
    const int cq = lane & 3;         // 0..3

    const int lm_off = ((((lane >> 3) & 1) * 8 + (lane & 7)) * GSTR
                        + (lane >> 4) * 8) * 2;   // bytes

    float acc[2][8][4];
    #pragma unroll
    for (int mt = 0; mt < 2; mt++)
        #pragma unroll
        for (int nt = 0; nt < 8; nt++)
            #pragma unroll
            for (int i = 0; i < 4; i++) acc[mt][nt][i] = 0.0f;

    #define GH_PREFETCH(kt, st)                                                \
    {                                                                          \
        __half* As_ = hsm + (st) * GSTAGE;                                     \
        __half* Bs_ = As_ + GBM * GSTR;                                        \
        const __half* Ag = A  + (size_t)bm * C_ + (kt) * GBK;                  \
        const __half* Bg = Bt + (size_t)bn * C_ + (kt) * GBK;                  \
        _Pragma("unroll")                                                      \
        for (int it = 0; it < 4; it++) {                                       \
            const int idx = it * 256 + tid;                                    \
            const int row = idx >> 3, g = (idx & 7) * 8;                       \
            cpasync16(As_ + row * GSTR + g, Ag + (size_t)row * C_ + g);        \
        }                                                                      \
        _Pragma("unroll")                                                      \
        for (int it = 0; it < 4; it++) {                                       \
            const int idx = it * 256 + tid;                                    \
            const int row = idx >> 3, g = (idx & 7) * 8;                       \
            cpasync16(Bs_ + row * GSTR + g, Bg + (size_t)row * C_ + g);        \
        }                                                                      \
    }

    GH_PREFETCH(0, 0);
    CP_COMMIT();

    for (int kt = 0; kt < GNKT; kt++) {
        if (kt + 1 < GNKT) {
            GH_PREFETCH(kt + 1, (kt + 1) & 1);
            CP_COMMIT();
            cp_wait<1>();
        } else {
            cp_wait<0>();
        }
        __syncthreads();

        const __half* As = hsm + (kt & 1) * GSTAGE;
        const __half* Bs = As + GBM * GSTR;
        const uint32_t as_u = (uint32_t)__cvta_generic_to_shared(As) + lm_off;
        const uint32_t bs_u = (uint32_t)__cvta_generic_to_shared(Bs) + lm_off;

        #pragma unroll
        for (int kk = 0; kk < 4; kk++) {            // K=16 steps
            const int kb = kk * 16;
            uint32_t af[2][4];
            #pragma unroll
            for (int mt = 0; mt < 2; mt++)
                ldsm_x4(af[mt][0], af[mt][1], af[mt][2], af[mt][3],
                        as_u + ((wm * 32 + mt * 16) * GSTR + kb) * 2);
            #pragma unroll
            for (int ntp = 0; ntp < 4; ntp++) {
                uint32_t b0e, b0o, b1e, b1o;
                ldsm_x4(b0e, b0o, b1e, b1o,
                        bs_u + ((wn * 64 + ntp * 16) * GSTR + kb) * 2);
                mma_f16(acc[0][2*ntp],     af[0], b0e, b1e);
                mma_f16(acc[0][2*ntp + 1], af[0], b0o, b1o);
                mma_f16(acc[1][2*ntp],     af[1], b0e, b1e);
                mma_f16(acc[1][2*ntp + 1], af[1], b0o, b1o);
            }
        }
        __syncthreads();
    }

    // ---- Epilogue ----
    if (MODE == 0) {
        float* o = (float*)Co;
        #pragma unroll
        for (int mt = 0; mt < 2; mt++) {
            const int row = bm + wm * 32 + mt * 16 + r;
            #pragma unroll
            for (int nt = 0; nt < 8; nt++) {
                const int col = bn + wn * 64 + nt * 8 + cq * 2;
                *(float2*)(o + (size_t)row * OSTR + col) =
                    make_float2(acc[mt][nt][0], acc[mt][nt][1]);
                *(float2*)(o + (size_t)(row + 8) * OSTR + col) =
                    make_float2(acc[mt][nt][2], acc[mt][nt][3]);
            }
        }
    } else {
        // Fused RoPE + RMSNorm for q/k cols (<2048); v passes through.
        __half* o = (__half*)Co;
        const bool is_v = (bn + wn * 64) >= 2048;
        #pragma unroll
        for (int mt = 0; mt < 2; mt++) {
            #pragma unroll
            for (int rh = 0; rh < 2; rh++) {      // c0,c1 = row r; c2,c3 = r+8
                const int row = bm + wm * 32 + mt * 16 + r + rh * 8;
                const int i0 = rh * 2, i1 = rh * 2 + 1;
                float ov[8][2];
                if (!is_v) {
                    const int t = row & (T_ - 1);
                    float ssum = 0.0f;
                    #pragma unroll
                    for (int nt = 0; nt < 4; nt++) {
                        const int d0 = nt * 8 + cq * 2;
                        const float2 cc = *(const float2*)&cosb[(size_t)t * D_ + d0];
                        const float2 sn = *(const float2*)&sinb[(size_t)t * D_ + d0];
                        const float x1a = acc[mt][nt][i0],     x1b = acc[mt][nt][i1];
                        const float x2a = acc[mt][nt + 4][i0], x2b = acc[mt][nt + 4][i1];
                        ov[nt][0]     = x1a * cc.x - x2a * sn.x;
                        ov[nt][1]     = x1b * cc.y - x2b * sn.y;
                        ov[nt + 4][0] = x1a * sn.x + x2a * cc.x;
                        ov[nt + 4][1] = x1b * sn.y + x2b * cc.y;
                        ssum += ov[nt][0]*ov[nt][0] + ov[nt][1]*ov[nt][1]
                              + ov[nt+4][0]*ov[nt+4][0] + ov[nt+4][1]*ov[nt+4][1];
                    }
                    ssum += __shfl_xor_sync(0xffffffffu, ssum, 1);
                    ssum += __shfl_xor_sync(0xffffffffu, ssum, 2);
                    const float rinv = rsqrtf(ssum * (1.0f / 64.0f) + 1e-6f);
                    #pragma unroll
                    for (int nt = 0; nt < 8; nt++) {
                        ov[nt][0] *= rinv; ov[nt][1] *= rinv;
                    }
                } else {
                    #pragma unroll
                    for (int nt = 0; nt < 8; nt++) {
                        ov[nt][0] = acc[mt][nt][i0];
                        ov[nt][1] = acc[mt][nt][i1];
                    }
                }
                #pragma unroll
                for (int nt = 0; nt < 8; nt++) {
                    const int col = bn + wn * 64 + nt * 8 + cq * 2;
                    __half2 hv = __floats2half2_rn(ov[nt][0], ov[nt][1]);
                    *(uint32_t*)(o + (size_t)row * OSTR + col) = *(uint32_t*)&hv;
                }
            }
        }
    }
}

// ----------------------------------------------------------------------------
// Flash attention v2: fixed-base softmax (scores bounded in [-8,8] after
// rmsnorm, so exp(s) is always fp16/fp32-safe; no online max, no rescale).
// P stays in registers (S C-frag == PV A-frag layout). 3-stage KV ring,
// one barrier per tile. 128-row q-tile, 64-row k-tile, 8 warps.
// ----------------------------------------------------------------------------
#define FSTRH 72
#define KVSTG (64 * FSTRH)                       // halfs per tensor per stage
#define FLASH_SMEM ((128*FSTRH + 3*2*KVSTG) * 2) // 73728 B
#define SOFTMAX_SCALE 0.180336880f               // 0.125 * log2(e)

__global__ __launch_bounds__(256) void flash_h(
    const __half* __restrict__ QKV, __half* __restrict__ O)
{
    extern __shared__ __half fsm[];
    __half* Pb = fsm;                            // [128][72] (Q staging only)
    const uint32_t pb_u = (uint32_t)__cvta_generic_to_shared(Pb);

    const int tid  = threadIdx.x;
    const int lane = tid & 31;
    const int warp = tid >> 5;         // 0..7
    const int r  = lane >> 2;          // 0..7
    const int cq = lane & 3;           // 0..3
    const int b = blockIdx.z, h = blockIdx.y;
    const int qi = (int)(gridDim.x - 1 - blockIdx.x);   // heavy blocks first
    const int q0 = qi * 128;
    const int m0 = warp * 16;

    const size_t rowstride = N3;           // 3072 halfs

    const int lm_off = ((((lane >> 3) & 1) * 8 + (lane & 7)) * FSTRH
                        + (lane >> 4) * 8) * 2;   // bytes (A/B-type ldmatrix)

    // trans-ldmatrix (V) per-lane decomposition
    const int lm_rr  = lane & 7;
    const int lm_sel = lane >> 3;
    const int lm_kad = ((lm_sel & 1) << 3) + lm_rr;
    const int lm_dad = (lm_sel >> 1) << 3;

    const __half* kbase = QKV + (size_t)(b * T_) * rowstride + C_   + h * D_;
    const __half* vbase = QKV + (size_t)(b * T_) * rowstride + 2*C_ + h * D_;

    #define KV_STAGE_K(s) (fsm + 128 * FSTRH + (s) * 2 * KVSTG)
    #define KV_STAGE_V(s) (KV_STAGE_K(s) + KVSTG)

    #define KVH_PREFETCH(jt, s)                                                \
    {                                                                          \
        __half* Kbuf = KV_STAGE_K(s);                                          \
        __half* Vbuf = KV_STAGE_V(s);                                          \
        _Pragma("unroll")                                                      \
        for (int it = 0; it < 2; it++) {                                       \
            const int idx = it * 256 + tid;                                    \
            const int row = idx >> 3;                                          \
            const int g   = (idx & 7) * 8;                                     \
            const __half* kg = kbase + (size_t)((jt) * 64 + row) * rowstride;  \
            const __half* vg = vbase + (size_t)((jt) * 64 + row) * rowstride;  \
            cpasync16(Kbuf + row * FSTRH + g, kg + g);                         \
            cpasync16(Vbuf + row * FSTRH + g, vg + g);                         \
        }                                                                      \
    }

    const int ntile = 2 * qi + 2;

    // ---- Stage Q into Pb (plain stores); prefetch K/V tiles 0,1 ----
    const __half* qb = QKV + (size_t)(b * T_ + q0) * rowstride + h * D_;
    #pragma unroll
    for (int it = 0; it < 4; it++) {
        const int idx = it * 256 + tid;
        const int row = idx >> 3;
        const int g   = (idx & 7) * 8;
        *(uint4*)&Pb[row * FSTRH + g] =
            *(const uint4*)(qb + (size_t)row * rowstride + g);
    }
    KVH_PREFETCH(0, 0); CP_COMMIT();
    if (ntile > 1) { KVH_PREFETCH(1, 1); }
    CP_COMMIT();
    __syncthreads();          // Q visible

    uint32_t qa[4][4];
    #pragma unroll
    for (int kk = 0; kk < 4; kk++)
        ldsm_x4(qa[kk][0], qa[kk][1], qa[kk][2], qa[kk][3],
                pb_u + (m0 * FSTRH + kk * 16) * 2 + lm_off);

    float l_lo = 0.0f, l_hi = 0.0f;
    float oacc[8][4];
    #pragma unroll
    for (int dt = 0; dt < 8; dt++)
        #pragma unroll
        for (int i = 0; i < 4; i++) oacc[dt][i] = 0.0f;

    for (int jt = 0; jt < ntile; jt++) {
        cp_wait<1>();          // stage jt data landed (groups: jt done)
        __syncthreads();       // all copies visible; readers of stage (jt+2)%3 done
        if (jt + 2 < ntile) { KVH_PREFETCH(jt + 2, (jt + 2) % 3); }
        CP_COMMIT();           // keep group numbering uniform

        const __half* Ks = KV_STAGE_K(jt % 3);
        const __half* Vs = KV_STAGE_V(jt % 3);
        const uint32_t ks_u = (uint32_t)__cvta_generic_to_shared(Ks) + lm_off;
        const uint32_t vs_u = (uint32_t)__cvta_generic_to_shared(Vs);
        const int k0 = jt * 64;

        // ---- S = Q @ K^T ----
        float sacc[8][4];
        #pragma unroll
        for (int nt = 0; nt < 8; nt++)
            #pragma unroll
            for (int i = 0; i < 4; i++) sacc[nt][i] = 0.0f;

        #pragma unroll
        for (int kk = 0; kk < 4; kk++) {
            const int kb2 = kk * 16;
            #pragma unroll
            for (int ntp = 0; ntp < 4; ntp++) {
                uint32_t b0e, b0o, b1e, b1o;
                ldsm_x4(b0e, b0o, b1e, b1o,
                        ks_u + (ntp * 16 * FSTRH + kb2) * 2);
                mma_f16(sacc[2*ntp],     qa[kk], b0e, b1e);
                mma_f16(sacc[2*ntp + 1], qa[kk], b0o, b1o);
            }
        }

        // ---- mask (diagonal tiles only) + exp2(s * scale) ----
        if (jt >= 2 * qi) {
            const int row_lo = q0 + m0 + r;
            const int row_hi = row_lo + 8;
            #pragma unroll
            for (int nt = 0; nt < 8; nt++) {
                const int c0 = k0 + nt * 8 + cq * 2;
                if (row_lo < c0    ) sacc[nt][0] = -1e30f;
                if (row_lo < c0 + 1) sacc[nt][1] = -1e30f;
                if (row_hi < c0    ) sacc[nt][2] = -1e30f;
                if (row_hi < c0 + 1) sacc[nt][3] = -1e30f;
            }
        }
        #pragma unroll
        for (int nt = 0; nt < 8; nt++) {
            sacc[nt][0] = ex2f(sacc[nt][0] * SOFTMAX_SCALE);
            sacc[nt][1] = ex2f(sacc[nt][1] * SOFTMAX_SCALE);
            sacc[nt][2] = ex2f(sacc[nt][2] * SOFTMAX_SCALE);
            sacc[nt][3] = ex2f(sacc[nt][3] * SOFTMAX_SCALE);
            l_lo += sacc[nt][0] + sacc[nt][1];
            l_hi += sacc[nt][2] + sacc[nt][3];
        }

        // ---- O += P @ V (P straight from registers; C-frag == A-frag) ----
        #pragma unroll
        for (int kk = 0; kk < 4; kk++) {
            uint32_t pa[4];
            pa[0] = packh2(sacc[2*kk][0],     sacc[2*kk][1]);
            pa[1] = packh2(sacc[2*kk][2],     sacc[2*kk][3]);
            pa[2] = packh2(sacc[2*kk + 1][0], sacc[2*kk + 1][1]);
            pa[3] = packh2(sacc[2*kk + 1][2], sacc[2*kk + 1][3]);
            const int kb2 = kk * 16;
            #pragma unroll
            for (int dtp = 0; dtp < 4; dtp++) {
                uint32_t v0, v1, v2, v3;
                const uint32_t addr = vs_u +
                    (uint32_t)(((kb2 + lm_kad) * FSTRH + dtp * 16 + lm_dad) * 2);
                ldsm_x4_t(v0, v1, v2, v3, addr);
                mma_f16(oacc[2*dtp],     pa, v0, v1);
                mma_f16(oacc[2*dtp + 1], pa, v2, v3);
            }
        }
    }

    // ---- final l reduction across cq group, normalize + store ----
    l_lo += __shfl_xor_sync(0xffffffffu, l_lo, 1);
    l_lo += __shfl_xor_sync(0xffffffffu, l_lo, 2);
    l_hi += __shfl_xor_sync(0xffffffffu, l_hi, 1);
    l_hi += __shfl_xor_sync(0xffffffffu, l_hi, 2);
    const float inv_lo = 1.0f / l_lo;
    const float inv_hi = 1.0f / l_hi;

    __half* ob = O + ((size_t)(b * T_ + q0) * H_ + h) * D_;
    #pragma unroll
    for (int dt = 0; dt < 8; dt++) {
        const int cc = dt * 8 + cq * 2;
        const uint32_t h0 = packh2(oacc[dt][0] * inv_lo, oacc[dt][1] * inv_lo);
        const uint32_t h1 = packh2(oacc[dt][2] * inv_hi, oacc[dt][3] * inv_hi);
        *(uint32_t*)(ob + (size_t)(m0 + r) * C_ + cc)     = h0;
        *(uint32_t*)(ob + (size_t)(m0 + r + 8) * C_ + cc) = h1;
    }
}

// ----------------------------------------------------------------------------
// Launch
// ----------------------------------------------------------------------------
extern "C" void kernel_launch(void* const* d_in, const int* in_sizes, int n_in,
                              void* d_out, int out_size)
{
    const float* x    = (const float*)d_in[0];
    const float* cosb = (const float*)d_in[1];
    const float* sinb = (const float*)d_in[2];
    const float* Wq   = (const float*)d_in[3];
    const float* Wk   = (const float*)d_in[4];
    const float* Wv   = (const float*)d_in[5];
    const float* Wp   = (const float*)d_in[6];
    float* out = (float*)d_out;

    __half *xh, *qkv, *yh, *wcat, *wpt;
    cudaGetSymbolAddress((void**)&xh,   g_xh);
    cudaGetSymbolAddress((void**)&qkv,  g_qkv);
    cudaGetSymbolAddress((void**)&yh,   g_yh);
    cudaGetSymbolAddress((void**)&wcat, g_wcat);
    cudaGetSymbolAddress((void**)&wpt,  g_wpt);

    cudaFuncSetAttribute(gemm2<1>,
        cudaFuncAttributeMaxDynamicSharedMemorySize, GEMM_SMEM);
    cudaFuncSetAttribute(gemm2<0>,
        cudaFuncAttributeMaxDynamicSharedMemorySize, GEMM_SMEM);
    cudaFuncSetAttribute(flash_h,
        cudaFuncAttributeMaxDynamicSharedMemorySize, FLASH_SMEM);

    // Pre-pass
    conv_xh<<<(M_ * C_) / (256 * 4), 256>>>(x, xh);
    dim3 tgrid(C_ / 32, C_ / 32, 4);
    trans_all<<<tgrid, 256>>>(Wq, Wk, Wv, Wp, wcat, wpt);

    // Fused QKV projection + RoPE + RMSNorm
    dim3 qgrid(N3 / GBN, M_ / GBM);   // (24, 32)
    gemm2<1><<<qgrid, 256, GEMM_SMEM>>>(xh, wcat, qkv, cosb, sinb);

    // Attention
    dim3 fgrid(T_ / 128, H_, B_);     // (16, 16, 2)
    flash_h<<<fgrid, 256, FLASH_SMEM>>>(qkv, yh);

    // Output projection (fp32 out)
    dim3 pgrid(C_ / GBN, M_ / GBM);   // (8, 32)
    gemm2<0><<<pgrid, 256, GEMM_SMEM>>>(yh, wpt, out, cosb, sinb);
}